// round 12
// baseline (speedup 1.0000x reference)
#include <cuda_runtime.h>
#include <cuda_fp16.h>
#include <cstdint>

#define C_CAPS 64
#define S_DIM 2048
#define H_DIM 512
#define M_ROWS (C_CAPS * S_DIM)   // 131072
#define NCHUNK 16
#define CHUNK_S (S_DIM / NCHUNK)  // 128
#define RSTG 16
#define NSTG (CHUNK_S / RSTG)     // 8
#define SLOTS 3

// ---------------- device scratch ----------------
__device__ __align__(128) __half g_whf[(size_t)H_DIM * H_DIM];  // pre-swizzled fp16 W
__device__ float g_norms[4 * M_ROWS];
__device__ float g_b[M_ROWS];
__device__ float g_u[C_CAPS * H_DIM];
__device__ float g_bc[C_CAPS];
__device__ float g_Mp[C_CAPS * NCHUNK];
__device__ float g_Zp[C_CAPS * NCHUNK];
__device__ float g_Wp[C_CAPS * NCHUNK];
__device__ float g_Vp[(size_t)C_CAPS * NCHUNK * H_DIM];
__device__ float g_craw[C_CAPS * H_DIM];
__device__ float g_sqp[C_CAPS * 8];

// ---------------- helpers ----------------
__device__ __forceinline__ uint32_t smem_u32(const void* p) {
    uint32_t a;
    asm("{ .reg .u64 t; cvta.to.shared.u64 t, %1; cvt.u32.u64 %0, t; }" : "=r"(a) : "l"(p));
    return a;
}
__device__ __forceinline__ void ldsm4(uint32_t* r, uint32_t addr) {
    asm volatile("ldmatrix.sync.aligned.m8n8.x4.shared.b16 {%0,%1,%2,%3}, [%4];"
        : "=r"(r[0]), "=r"(r[1]), "=r"(r[2]), "=r"(r[3]) : "r"(addr));
}
// f16-accumulator HMMA
__device__ __forceinline__ void mma16816h(uint32_t* d, const uint32_t* a, const uint32_t* b) {
    asm volatile("mma.sync.aligned.m16n8k16.row.col.f16.f16.f16.f16 "
        "{%0,%1}, {%2,%3,%4,%5}, {%6,%7}, {%0,%1};"
        : "+r"(d[0]), "+r"(d[1])
        : "r"(a[0]), "r"(a[1]), "r"(a[2]), "r"(a[3]), "r"(b[0]), "r"(b[1]));
}
__device__ __forceinline__ void sts128(uint32_t addr, uint4 v) {
    asm volatile("st.shared.v4.b32 [%0], {%1,%2,%3,%4};"
        :: "r"(addr), "r"(v.x), "r"(v.y), "r"(v.z), "r"(v.w) : "memory");
}
#define CP_ASYNC16(dst, src) \
    asm volatile("cp.async.cg.shared.global [%0], [%1], 16;" :: "r"(dst), "l"(src) : "memory")
#define CP_COMMIT() asm volatile("cp.async.commit_group;" ::: "memory")
#define CP_WAIT(n)  asm volatile("cp.async.wait_group %0;" :: "n"(n) : "memory")

__device__ __forceinline__ uint32_t packh2(float x, float y) {
    __half2 h = __floats2half2_rn(x, y);
    return *(uint32_t*)&h;
}
__device__ __forceinline__ uint32_t tswz(uint32_t row, uint32_t kc) {
    return row * 64u + ((kc ^ ((row >> 1) & 3u)) << 4);
}

// ============================================================================
// convw: W fp32 -> pre-swizzled fp16 tiles (8KB blocks [128 rows x 32 k]).
// ============================================================================
__global__ void convw_kernel(const float* __restrict__ W) {
    int g = blockIdx.x * 256 + threadIdx.x;
    int n = g >> 7, ch = g & 127;
    int kt = ch >> 3, kc = (ch >> 1) & 3, half = ch & 1;
    int bn = n >> 7, nrow = n & 127;
    float4 v = *(const float4*)&W[(size_t)n * 512 + ch * 4];
    uint2 hi;
    hi.x = packh2(v.x, v.y);
    hi.y = packh2(v.z, v.w);
    size_t dst = ((size_t)(bn * 16 + kt) << 13) + tswz(nrow, kc) + half * 8;
    *(uint2*)((char*)g_whf + dst) = hi;
}

// ============================================================================
// GEMM (norms only): fp16 x * fp16 W, f16 accumulate. Tile 128x128, BK=32,
// 8 warps, double-buffered. B via cp.async from pre-swizzled W.
// ============================================================================
#define GSM_STAGE 16384
#define GSM_TOTAL (2 * GSM_STAGE + 512)

__device__ __forceinline__ void issueB(uint32_t stg, int bn, int kt, int t) {
    size_t tile = (size_t)(bn * 16 + kt) << 13;
    const char* sh = (const char*)g_whf + tile + t * 32;
    CP_ASYNC16(stg + 8192 + t * 32, sh);
    CP_ASYNC16(stg + 8192 + t * 32 + 16, sh + 16);
}

__global__ void __launch_bounds__(256, 2) gemm_norms(
    const float* __restrict__ x, const float* __restrict__ bias)
{
    extern __shared__ __align__(1024) char smem[];
    const uint32_t sb = smem_u32(smem);

    const int t = threadIdx.x, l = t & 31, wid = t >> 5;
    const int wm = wid & 3, wn = wid >> 2;
    const int bn = blockIdx.x, mtile = blockIdx.y;

    const int c0row = t >> 2, ckc = t & 3;
    const float* ag0 = x + ((size_t)mtile * 128 + c0row) * 512 + ckc * 8;
    const float* ag1 = x + ((size_t)mtile * 128 + c0row + 64) * 512 + ckc * 8;
    const uint32_t so0 = tswz(c0row, ckc);
    const uint32_t so1 = tswz(c0row + 64, ckc);

    uint32_t aoffA[2][2], aoffB[4][2];
#pragma unroll
    for (int mt = 0; mt < 2; mt++)
#pragma unroll
        for (int ks = 0; ks < 2; ks++) {
            uint32_t m = wm * 32 + mt * 16 + ((l >> 3) & 1) * 8 + (l & 7);
            aoffA[mt][ks] = tswz(m, ks * 2 + (l >> 4));
        }
#pragma unroll
    for (int nt2 = 0; nt2 < 4; nt2++)
#pragma unroll
        for (int ks = 0; ks < 2; ks++) {
            uint32_t n = wn * 64 + nt2 * 16 + ((l >> 4) & 1) * 8 + (l & 7);
            aoffB[nt2][ks] = tswz(n, ks * 2 + ((l >> 3) & 1));
        }

    uint32_t acc[2][8][2];
#pragma unroll
    for (int mt = 0; mt < 2; mt++)
#pragma unroll
        for (int nt = 0; nt < 8; nt++) { acc[mt][nt][0] = 0u; acc[mt][nt][1] = 0u; }

    issueB(sb, bn, 0, t);
    CP_COMMIT();
    float4 pa[2][2];
    pa[0][0] = *(const float4*)(ag0); pa[0][1] = *(const float4*)(ag0 + 4);
    pa[1][0] = *(const float4*)(ag1); pa[1][1] = *(const float4*)(ag1 + 4);

    for (int kt = 0; kt < 16; kt++) {
        const uint32_t stg = sb + (kt & 1) * GSM_STAGE;
        {
            uint4 h0, h1;
            h0.x = packh2(pa[0][0].x, pa[0][0].y); h0.y = packh2(pa[0][0].z, pa[0][0].w);
            h0.z = packh2(pa[0][1].x, pa[0][1].y); h0.w = packh2(pa[0][1].z, pa[0][1].w);
            h1.x = packh2(pa[1][0].x, pa[1][0].y); h1.y = packh2(pa[1][0].z, pa[1][0].w);
            h1.z = packh2(pa[1][1].x, pa[1][1].y); h1.w = packh2(pa[1][1].z, pa[1][1].w);
            sts128(stg + so0, h0);
            sts128(stg + so1, h1);
        }
        if (kt < 15) {
            issueB(sb + ((kt + 1) & 1) * GSM_STAGE, bn, kt + 1, t);
            CP_COMMIT();
            CP_WAIT(1);
        } else {
            CP_WAIT(0);
        }
        __syncthreads();

        if (kt < 15) {
            int ko = (kt + 1) * 32;
            pa[0][0] = *(const float4*)(ag0 + ko); pa[0][1] = *(const float4*)(ag0 + ko + 4);
            pa[1][0] = *(const float4*)(ag1 + ko); pa[1][1] = *(const float4*)(ag1 + ko + 4);
        }

#pragma unroll
        for (int ks = 0; ks < 2; ks++) {
            uint32_t ah[2][4], bh[4][4];
#pragma unroll
            for (int mt = 0; mt < 2; mt++) ldsm4(ah[mt], stg + aoffA[mt][ks]);
#pragma unroll
            for (int nt2 = 0; nt2 < 4; nt2++) ldsm4(bh[nt2], stg + 8192 + aoffB[nt2][ks]);
#pragma unroll
            for (int mt = 0; mt < 2; mt++)
#pragma unroll
                for (int nt = 0; nt < 8; nt++)
                    mma16816h(acc[mt][nt], ah[mt], &bh[nt >> 1][(nt & 1) * 2]);
        }
        __syncthreads();
    }

    float* norm_sm = (float*)(smem + 2 * GSM_STAGE);
    if (t < 128) norm_sm[t] = 0.f;
    __syncthreads();

    float2 bias2[8];
#pragma unroll
    for (int nt = 0; nt < 8; nt++)
        bias2[nt] = *(const float2*)&bias[bn * 128 + wn * 64 + nt * 8 + (l & 3) * 2];

#pragma unroll
    for (int mt = 0; mt < 2; mt++)
#pragma unroll
        for (int half = 0; half < 2; half++) {
            int r = wm * 32 + mt * 16 + (l >> 2) + half * 8;
            float ss = 0.f;
#pragma unroll
            for (int nt = 0; nt < 8; nt++) {
                float2 v = __half22float2(*(__half2*)&acc[mt][nt][half]);
                float vx = v.x + bias2[nt].x;
                float vy = v.y + bias2[nt].y;
                ss += vx * vx + vy * vy;
            }
            ss += __shfl_xor_sync(0xffffffffu, ss, 1);
            ss += __shfl_xor_sync(0xffffffffu, ss, 2);
            if ((l & 3) == 0) atomicAdd(&norm_sm[r], ss);
        }
    __syncthreads();
    if (t < 128)
        g_norms[(size_t)bn * M_ROWS + (size_t)mtile * 128 + t] = norm_sm[t];
}

// ============================================================================
// Sweep: 3-slot cp.async ring, 16-row stages (96KB dynamic smem, 2 CTAs/SM).
// ============================================================================
#define SWEEP_SMEM (SLOTS * RSTG * 512 * 4)

__device__ __forceinline__ void sweep_issue(const float* src, float* slot, int t) {
    uint32_t dst = smem_u32(slot);
#pragma unroll
    for (int i = 0; i < 8; i++) {
        int idx = t + 256 * i;
        CP_ASYNC16(dst + idx * 16, src + idx * 4);
    }
    CP_COMMIT();
}

__global__ void __launch_bounds__(256, 2) sweep_pass(const float* __restrict__ x, int do_dot) {
    extern __shared__ __align__(16) float tiles[];
    __shared__ float usm[512];
    __shared__ float bst[RSTG], sst[RSTG], wst[RSTG];
    __shared__ float runMs, Zsh, Wsh, fsh, bcs;

    const int c = blockIdx.y, chunk = blockIdx.x;
    const int t = threadIdx.x, wid = t >> 5, lane = t & 31;

    usm[t]       = do_dot ? g_u[c * 512 + t] : 0.f;
    usm[t + 256] = do_dot ? g_u[c * 512 + t + 256] : 0.f;
    if (t == 0) { runMs = -1e30f; Zsh = 0.f; Wsh = 0.f; bcs = do_dot ? g_bc[c] : 0.f; }

    const size_t rowbase = (size_t)c * S_DIM + (size_t)chunk * CHUNK_S;
    float ax = 0.f, ay = 0.f;

    sweep_issue(x + rowbase * 512, tiles, t);
    sweep_issue(x + (rowbase + RSTG) * 512, tiles + RSTG * 512, t);

    for (int st = 0; st < NSTG; st++) {
        if (st < NSTG - 1) { CP_WAIT(1); } else { CP_WAIT(0); }
        __syncthreads();
        float* tile = tiles + (st % SLOTS) * (RSTG * 512);

        if (st + 2 < NSTG)
            sweep_issue(x + (rowbase + (size_t)(st + 2) * RSTG) * 512,
                        tiles + ((st + 2) % SLOTS) * (RSTG * 512), t);

#pragma unroll
        for (int rr = 0; rr < 2; rr++) {
            int rl = wid * 2 + rr;
            float dot = 0.f;
            if (do_dot) {
                const float4* tr = (const float4*)(tile + rl * 512);
#pragma unroll
                for (int j = 0; j < 4; j++) {
                    float4 v = tr[lane + 32 * j];
                    float4 cv = *(const float4*)&usm[(lane + 32 * j) * 4];
                    dot += v.x * cv.x + v.y * cv.y + v.z * cv.z + v.w * cv.w;
                }
#pragma unroll
                for (int off = 16; off > 0; off >>= 1)
                    dot += __shfl_xor_sync(0xffffffffu, dot, off);
            }
            if (lane == 0) {
                size_t row = rowbase + st * RSTG + rl;
                float sq = g_norms[row] + g_norms[M_ROWS + row]
                         + g_norms[2 * M_ROWS + row] + g_norms[3 * M_ROWS + row];
                float scale = (sq / (1.f + sq)) * rsqrtf(sq + 1e-7f);
                float bv;
                if (do_dot) {
                    bv = g_b[row] + scale * (dot + bcs);
                    g_b[row] = bv;
                } else {
                    bv = 0.f;
                }
                bst[rl] = bv;
                sst[rl] = scale;
            }
        }
        __syncthreads();

        if (t < 32) {
            float v = (lane < RSTG) ? bst[lane] : -1e30f;
            float m = v;
#pragma unroll
            for (int off = 16; off > 0; off >>= 1)
                m = fmaxf(m, __shfl_xor_sync(0xffffffffu, m, off));
            float rm = runMs;
            float nm = fmaxf(rm, m);
            float w = __expf(v - nm);
            float zst = w;
#pragma unroll
            for (int off = 16; off > 0; off >>= 1)
                zst += __shfl_xor_sync(0xffffffffu, zst, off);
            float wsv = (lane < RSTG) ? w * sst[lane] : 0.f;
            float wss = wsv;
#pragma unroll
            for (int off = 16; off > 0; off >>= 1)
                wss += __shfl_xor_sync(0xffffffffu, wss, off);
            if (lane < RSTG) wst[lane] = wsv;
            if (lane == 0) {
                float f = __expf(rm - nm);
                fsh = f;
                Zsh = Zsh * f + zst;
                Wsh = Wsh * f + wss;
                runMs = nm;
            }
        }
        __syncthreads();

        float f = fsh;
        ax *= f; ay *= f;
#pragma unroll
        for (int r = 0; r < RSTG; r++) {
            float w = wst[r];
            float2 v = *(const float2*)(tile + r * 512 + 2 * t);
            ax += w * v.x;
            ay += w * v.y;
        }
    }

    int pc = c * NCHUNK + chunk;
    *(float2*)&g_Vp[(size_t)pc * 512 + 2 * t] = make_float2(ax, ay);
    if (t == 0) { g_Mp[pc] = runMs; g_Zp[pc] = Zsh; g_Wp[pc] = Wsh; }
}

// ============================================================================
// cmat (fused reduce): y from chunk partials; craw = y.W_o + bias_o*wts;
// partial sumsq per (c, ob). grid (8, 64): 64 outputs per block, warp per 8.
// ============================================================================
__global__ void __launch_bounds__(256) cmat_kernel(
    const float* __restrict__ W, const float* __restrict__ bias)
{
    const int ob = blockIdx.x, c = blockIdx.y;
    const int t = threadIdx.x, wid = t >> 5, lane = t & 31;
    __shared__ float ysm[512];
    __shared__ float sk[NCHUNK];
    __shared__ float ssp[8];
    __shared__ float Zs, Wts;

    if (t == 0) {
        float M = g_Mp[c * NCHUNK];
#pragma unroll
        for (int k = 1; k < NCHUNK; k++) M = fmaxf(M, g_Mp[c * NCHUNK + k]);
        float Z = 0.f, Wt = 0.f;
#pragma unroll
        for (int k = 0; k < NCHUNK; k++) {
            float e = __expf(g_Mp[c * NCHUNK + k] - M);
            sk[k] = e;
            Z  += g_Zp[c * NCHUNK + k] * e;
            Wt += g_Wp[c * NCHUNK + k] * e;
        }
        Zs = Z;
        Wts = Wt / Z;
    }
    __syncthreads();

    {
        float w0 = 0.f, w1 = 0.f;
#pragma unroll
        for (int k = 0; k < NCHUNK; k++) {
            float e = sk[k];
            float2 v = *(const float2*)&g_Vp[((size_t)(c * NCHUNK + k)) * 512 + 2 * t];
            w0 += e * v.x;
            w1 += e * v.y;
        }
        float invZ = 1.f / Zs;
        ysm[2 * t] = w0 * invZ;
        ysm[2 * t + 1] = w1 * invZ;
    }
    __syncthreads();

    const float Wts_l = Wts;
    float ss = 0.f;
#pragma unroll
    for (int i = 0; i < 8; i++) {
        int o = ob * 64 + wid * 8 + i;
        const float4* wr = (const float4*)(W + (size_t)o * 512);
        float d = 0.f;
#pragma unroll
        for (int g = 0; g < 4; g++) {
            float4 a = wr[lane + 32 * g];
            float4 b = *(const float4*)&ysm[(lane + 32 * g) * 4];
            d += a.x * b.x + a.y * b.y + a.z * b.z + a.w * b.w;
        }
#pragma unroll
        for (int off = 16; off > 0; off >>= 1)
            d += __shfl_xor_sync(0xffffffffu, d, off);
        if (lane == 0) {
            float cr = d + bias[o] * Wts_l;
            g_craw[c * 512 + o] = cr;
            ss += cr * cr;
        }
    }
    if (lane == 0) ssp[wid] = ss;
    __syncthreads();
    if (t == 0) {
        float s = 0.f;
#pragma unroll
        for (int k = 0; k < 8; k++) s += ssp[k];
        g_sqp[c * 8 + ob] = s;
    }
}

// ============================================================================
// ustep: scale; u = scale * W^T craw ; bc = scale*(bias.craw).
// grid (8, 64): 64 h-columns per block; o-loop split 8 ways (64 each).
// ============================================================================
__global__ void __launch_bounds__(256) ustep_kernel(
    const float* __restrict__ W, const float* __restrict__ bias)
{
    const int ob = blockIdx.x, c = blockIdx.y;
    const int t = threadIdx.x;
    const int og = t >> 5, cp = t & 31;

    __shared__ float csm[512];
    __shared__ float2 up[8][32];
    __shared__ float scsh;
    __shared__ float red2[8];

    csm[t]       = g_craw[c * 512 + t];
    csm[t + 256] = g_craw[c * 512 + t + 256];
    if (t == 0) {
        float sq = 0.f;
#pragma unroll
        for (int k = 0; k < 8; k++) sq += g_sqp[c * 8 + k];
        scsh = (sq / (1.f + sq)) * rsqrtf(sq + 1e-7f);
    }
    __syncthreads();
    const float scale = scsh;

    float u0 = 0.f, u1 = 0.f;
    const float* wp = W + (size_t)(og * 64) * 512 + ob * 64 + cp * 2;
#pragma unroll 8
    for (int o = 0; o < 64; o++) {
        float co = csm[og * 64 + o];
        float2 wv = *(const float2*)(wp + (size_t)o * 512);
        u0 += co * wv.x;
        u1 += co * wv.y;
    }
    up[og][cp] = make_float2(u0, u1);
    __syncthreads();

    if (t < 32) {
        float sx = 0.f, sy = 0.f;
#pragma unroll
        for (int k = 0; k < 8; k++) { sx += up[k][t].x; sy += up[k][t].y; }
        *(float2*)&g_u[c * 512 + ob * 64 + t * 2] =
            make_float2(scale * sx, scale * sy);
    }

    if (ob == 0) {
        float p = bias[t] * csm[t] + bias[t + 256] * csm[t + 256];
#pragma unroll
        for (int off = 16; off > 0; off >>= 1)
            p += __shfl_xor_sync(0xffffffffu, p, off);
        if ((t & 31) == 0) red2[t >> 5] = p;
        __syncthreads();
        if (t == 0) {
            float pp = 0.f;
#pragma unroll
            for (int k = 0; k < 8; k++) pp += red2[k];
            g_bc[c] = scale * pp;
        }
    }
}

// ============================================================================
__global__ void __launch_bounds__(256) out_kernel(float* __restrict__ out) {
    const int c = blockIdx.x, t = threadIdx.x;
    __shared__ float scsh;
    if (t == 0) {
        float sq = 0.f;
#pragma unroll
        for (int k = 0; k < 8; k++) sq += g_sqp[c * 8 + k];
        scsh = (sq / (1.f + sq)) * rsqrtf(sq + 1e-7f);
    }
    __syncthreads();
    out[c * 512 + t]       = scsh * g_craw[c * 512 + t];
    out[c * 512 + t + 256] = scsh * g_craw[c * 512 + t + 256];
}

// ============================================================================
extern "C" void kernel_launch(void* const* d_in, const int* in_sizes, int n_in,
                              void* d_out, int out_size) {
    const float* x    = (const float*)d_in[0];
    const float* W    = (const float*)d_in[1];
    const float* bias = (const float*)d_in[2];
    float* out = (float*)d_out;

    void* pb = nullptr; cudaGetSymbolAddress(&pb, g_b);
    cudaMemsetAsync(pb, 0, (size_t)M_ROWS * sizeof(float));

    convw_kernel<<<256, 256>>>(W);

    static bool attr_done = false;
    if (!attr_done) {
        cudaFuncSetAttribute(gemm_norms, cudaFuncAttributeMaxDynamicSharedMemorySize, GSM_TOTAL);
        cudaFuncSetAttribute(sweep_pass, cudaFuncAttributeMaxDynamicSharedMemorySize, SWEEP_SMEM);
        attr_done = true;
    }
    gemm_norms<<<dim3(4, 1024), 256, GSM_TOTAL>>>(x, bias);

    for (int it = 0; it < 3; ++it) {
        sweep_pass<<<dim3(NCHUNK, C_CAPS), 256, SWEEP_SMEM>>>(x, it > 0 ? 1 : 0);
        cmat_kernel<<<dim3(8, C_CAPS), 256>>>(W, bias);
        if (it < 2) ustep_kernel<<<dim3(8, C_CAPS), 256>>>(W, bias);
        else        out_kernel<<<C_CAPS, 256>>>(out);
    }
}

// round 13
// speedup vs baseline: 1.0666x; 1.0666x over previous
#include <cuda_runtime.h>
#include <cuda_fp16.h>
#include <cstdint>

#define C_CAPS 64
#define S_DIM 2048
#define H_DIM 512
#define M_ROWS (C_CAPS * S_DIM)   // 131072
#define NCHUNK 16
#define CHUNK_S (S_DIM / NCHUNK)  // 128
#define RSTG 32
#define NSTG (CHUNK_S / RSTG)     // 4
#define SLOTS 3

// ---------------- device scratch ----------------
__device__ __align__(128) __half g_whf[(size_t)H_DIM * H_DIM];   // pre-swizzled fp16 W
__device__ __align__(128) __half g_xhf[(size_t)M_ROWS * H_DIM];  // linear fp16 x (134 MB)
__device__ float g_norms[4 * M_ROWS];
__device__ float g_b[M_ROWS];
__device__ float g_u[C_CAPS * H_DIM];
__device__ float g_bc[C_CAPS];
__device__ float g_Mp[C_CAPS * NCHUNK];
__device__ float g_Zp[C_CAPS * NCHUNK];
__device__ float g_Wp[C_CAPS * NCHUNK];
__device__ float g_Vp[(size_t)C_CAPS * NCHUNK * H_DIM];
__device__ float g_craw[C_CAPS * H_DIM];
__device__ float g_sqp[C_CAPS * 8];

// ---------------- helpers ----------------
__device__ __forceinline__ uint32_t smem_u32(const void* p) {
    uint32_t a;
    asm("{ .reg .u64 t; cvta.to.shared.u64 t, %1; cvt.u32.u64 %0, t; }" : "=r"(a) : "l"(p));
    return a;
}
__device__ __forceinline__ void ldsm4(uint32_t* r, uint32_t addr) {
    asm volatile("ldmatrix.sync.aligned.m8n8.x4.shared.b16 {%0,%1,%2,%3}, [%4];"
        : "=r"(r[0]), "=r"(r[1]), "=r"(r[2]), "=r"(r[3]) : "r"(addr));
}
__device__ __forceinline__ void mma16816h(uint32_t* d, const uint32_t* a, const uint32_t* b) {
    asm volatile("mma.sync.aligned.m16n8k16.row.col.f16.f16.f16.f16 "
        "{%0,%1}, {%2,%3,%4,%5}, {%6,%7}, {%0,%1};"
        : "+r"(d[0]), "+r"(d[1])
        : "r"(a[0]), "r"(a[1]), "r"(a[2]), "r"(a[3]), "r"(b[0]), "r"(b[1]));
}
__device__ __forceinline__ void sts128(uint32_t addr, uint4 v) {
    asm volatile("st.shared.v4.b32 [%0], {%1,%2,%3,%4};"
        :: "r"(addr), "r"(v.x), "r"(v.y), "r"(v.z), "r"(v.w) : "memory");
}
#define CP_ASYNC16(dst, src) \
    asm volatile("cp.async.cg.shared.global [%0], [%1], 16;" :: "r"(dst), "l"(src) : "memory")
#define CP_COMMIT() asm volatile("cp.async.commit_group;" ::: "memory")
#define CP_WAIT(n)  asm volatile("cp.async.wait_group %0;" :: "n"(n) : "memory")

__device__ __forceinline__ uint32_t packh2(float x, float y) {
    __half2 h = __floats2half2_rn(x, y);
    return *(uint32_t*)&h;
}
__device__ __forceinline__ uint32_t tswz(uint32_t row, uint32_t kc) {
    return row * 64u + ((kc ^ ((row >> 1) & 3u)) << 4);
}

// ============================================================================
// convw: W fp32 -> pre-swizzled fp16 tiles (8KB blocks [128 rows x 32 k]).
// ============================================================================
__global__ void convw_kernel(const float* __restrict__ W) {
    int g = blockIdx.x * 256 + threadIdx.x;
    int n = g >> 7, ch = g & 127;
    int kt = ch >> 3, kc = (ch >> 1) & 3, half = ch & 1;
    int bn = n >> 7, nrow = n & 127;
    float4 v = *(const float4*)&W[(size_t)n * 512 + ch * 4];
    uint2 hi;
    hi.x = packh2(v.x, v.y);
    hi.y = packh2(v.z, v.w);
    size_t dst = ((size_t)(bn * 16 + kt) << 13) + tswz(nrow, kc) + half * 8;
    *(uint2*)((char*)g_whf + dst) = hi;
}

// ============================================================================
// GEMM (norms only) + fp16-x export: fp16 HMMA, f16 accumulate.
// bn==0 blocks also write the converted A chunks to g_xhf (linear layout).
// ============================================================================
#define GSM_STAGE 16384
#define GSM_TOTAL (2 * GSM_STAGE + 512)

__device__ __forceinline__ void issueB(uint32_t stg, int bn, int kt, int t) {
    size_t tile = (size_t)(bn * 16 + kt) << 13;
    const char* sh = (const char*)g_whf + tile + t * 32;
    CP_ASYNC16(stg + 8192 + t * 32, sh);
    CP_ASYNC16(stg + 8192 + t * 32 + 16, sh + 16);
}

__global__ void __launch_bounds__(256, 2) gemm_norms(
    const float* __restrict__ x, const float* __restrict__ bias)
{
    extern __shared__ __align__(1024) char smem[];
    const uint32_t sb = smem_u32(smem);

    const int t = threadIdx.x, l = t & 31, wid = t >> 5;
    const int wm = wid & 3, wn = wid >> 2;
    const int bn = blockIdx.x, mtile = blockIdx.y;

    const int c0row = t >> 2, ckc = t & 3;
    const float* ag0 = x + ((size_t)mtile * 128 + c0row) * 512 + ckc * 8;
    const float* ag1 = x + ((size_t)mtile * 128 + c0row + 64) * 512 + ckc * 8;
    const uint32_t so0 = tswz(c0row, ckc);
    const uint32_t so1 = tswz(c0row + 64, ckc);

    __half* xo0 = g_xhf + ((size_t)mtile * 128 + c0row) * 512 + ckc * 8;
    __half* xo1 = g_xhf + ((size_t)mtile * 128 + c0row + 64) * 512 + ckc * 8;

    uint32_t aoffA[2][2], aoffB[4][2];
#pragma unroll
    for (int mt = 0; mt < 2; mt++)
#pragma unroll
        for (int ks = 0; ks < 2; ks++) {
            uint32_t m = wm * 32 + mt * 16 + ((l >> 3) & 1) * 8 + (l & 7);
            aoffA[mt][ks] = tswz(m, ks * 2 + (l >> 4));
        }
#pragma unroll
    for (int nt2 = 0; nt2 < 4; nt2++)
#pragma unroll
        for (int ks = 0; ks < 2; ks++) {
            uint32_t n = wn * 64 + nt2 * 16 + ((l >> 4) & 1) * 8 + (l & 7);
            aoffB[nt2][ks] = tswz(n, ks * 2 + ((l >> 3) & 1));
        }

    uint32_t acc[2][8][2];
#pragma unroll
    for (int mt = 0; mt < 2; mt++)
#pragma unroll
        for (int nt = 0; nt < 8; nt++) { acc[mt][nt][0] = 0u; acc[mt][nt][1] = 0u; }

    issueB(sb, bn, 0, t);
    CP_COMMIT();
    float4 pa[2][2];
    pa[0][0] = *(const float4*)(ag0); pa[0][1] = *(const float4*)(ag0 + 4);
    pa[1][0] = *(const float4*)(ag1); pa[1][1] = *(const float4*)(ag1 + 4);

    for (int kt = 0; kt < 16; kt++) {
        const uint32_t stg = sb + (kt & 1) * GSM_STAGE;
        {
            uint4 h0, h1;
            h0.x = packh2(pa[0][0].x, pa[0][0].y); h0.y = packh2(pa[0][0].z, pa[0][0].w);
            h0.z = packh2(pa[0][1].x, pa[0][1].y); h0.w = packh2(pa[0][1].z, pa[0][1].w);
            h1.x = packh2(pa[1][0].x, pa[1][0].y); h1.y = packh2(pa[1][0].z, pa[1][0].w);
            h1.z = packh2(pa[1][1].x, pa[1][1].y); h1.w = packh2(pa[1][1].z, pa[1][1].w);
            sts128(stg + so0, h0);
            sts128(stg + so1, h1);
            if (bn == 0) {   // export fp16 x (linear) for the sweeps
                *(uint4*)(xo0 + kt * 32) = h0;
                *(uint4*)(xo1 + kt * 32) = h1;
            }
        }
        if (kt < 15) {
            issueB(sb + ((kt + 1) & 1) * GSM_STAGE, bn, kt + 1, t);
            CP_COMMIT();
            CP_WAIT(1);
        } else {
            CP_WAIT(0);
        }
        __syncthreads();

        if (kt < 15) {
            int ko = (kt + 1) * 32;
            pa[0][0] = *(const float4*)(ag0 + ko); pa[0][1] = *(const float4*)(ag0 + ko + 4);
            pa[1][0] = *(const float4*)(ag1 + ko); pa[1][1] = *(const float4*)(ag1 + ko + 4);
        }

#pragma unroll
        for (int ks = 0; ks < 2; ks++) {
            uint32_t ah[2][4], bh[4][4];
#pragma unroll
            for (int mt = 0; mt < 2; mt++) ldsm4(ah[mt], stg + aoffA[mt][ks]);
#pragma unroll
            for (int nt2 = 0; nt2 < 4; nt2++) ldsm4(bh[nt2], stg + 8192 + aoffB[nt2][ks]);
#pragma unroll
            for (int mt = 0; mt < 2; mt++)
#pragma unroll
                for (int nt = 0; nt < 8; nt++)
                    mma16816h(acc[mt][nt], ah[mt], &bh[nt >> 1][(nt & 1) * 2]);
        }
        __syncthreads();
    }

    float* norm_sm = (float*)(smem + 2 * GSM_STAGE);
    if (t < 128) norm_sm[t] = 0.f;
    __syncthreads();

    float2 bias2[8];
#pragma unroll
    for (int nt = 0; nt < 8; nt++)
        bias2[nt] = *(const float2*)&bias[bn * 128 + wn * 64 + nt * 8 + (l & 3) * 2];

#pragma unroll
    for (int mt = 0; mt < 2; mt++)
#pragma unroll
        for (int half = 0; half < 2; half++) {
            int r = wm * 32 + mt * 16 + (l >> 2) + half * 8;
            float ss = 0.f;
#pragma unroll
            for (int nt = 0; nt < 8; nt++) {
                float2 v = __half22float2(*(__half2*)&acc[mt][nt][half]);
                float vx = v.x + bias2[nt].x;
                float vy = v.y + bias2[nt].y;
                ss += vx * vx + vy * vy;
            }
            ss += __shfl_xor_sync(0xffffffffu, ss, 1);
            ss += __shfl_xor_sync(0xffffffffu, ss, 2);
            if ((l & 3) == 0) atomicAdd(&norm_sm[r], ss);
        }
    __syncthreads();
    if (t < 128)
        g_norms[(size_t)bn * M_ROWS + (size_t)mtile * 128 + t] = norm_sm[t];
}

// ============================================================================
// Sweep over fp16 x: 3-slot cp.async ring, 32-row stages (96KB smem, occ 2).
// ============================================================================
#define SWEEP_SMEM (SLOTS * RSTG * 512 * 2)

__device__ __forceinline__ void sweep_issue(const __half* src, __half* slot, int t) {
    uint32_t dst = smem_u32(slot);
    const char* s = (const char*)src;
#pragma unroll
    for (int i = 0; i < 8; i++) {
        int idx = t + 256 * i;
        CP_ASYNC16(dst + idx * 16, s + idx * 16);
    }
    CP_COMMIT();
}

__global__ void __launch_bounds__(256, 2) sweep_pass(int do_dot) {
    extern __shared__ __align__(16) __half tiles[];
    __shared__ float usm[512];
    __shared__ float bst[RSTG], sst[RSTG], wst[RSTG];
    __shared__ float runMs, Zsh, Wsh, fsh, bcs;

    const int c = blockIdx.y, chunk = blockIdx.x;
    const int t = threadIdx.x, wid = t >> 5, lane = t & 31;

    usm[t]       = do_dot ? g_u[c * 512 + t] : 0.f;
    usm[t + 256] = do_dot ? g_u[c * 512 + t + 256] : 0.f;
    if (t == 0) { runMs = -1e30f; Zsh = 0.f; Wsh = 0.f; bcs = do_dot ? g_bc[c] : 0.f; }

    const size_t rowbase = (size_t)c * S_DIM + (size_t)chunk * CHUNK_S;
    const __half* xsrc = g_xhf + rowbase * 512;
    float ax = 0.f, ay = 0.f;

    sweep_issue(xsrc, tiles, t);
    sweep_issue(xsrc + (size_t)RSTG * 512, tiles + RSTG * 512, t);

    for (int st = 0; st < NSTG; st++) {
        if (st < NSTG - 1) { CP_WAIT(1); } else { CP_WAIT(0); }
        __syncthreads();
        __half* tile = tiles + (st % SLOTS) * (RSTG * 512);

        if (st + 2 < NSTG)
            sweep_issue(xsrc + (size_t)(st + 2) * RSTG * 512,
                        tiles + ((st + 2) % SLOTS) * (RSTG * 512), t);

        // dots: each warp handles 4 rows
#pragma unroll
        for (int rr = 0; rr < 4; rr++) {
            int rl = wid * 4 + rr;
            float dot = 0.f;
            if (do_dot) {
                const __half2* tr = (const __half2*)(tile + rl * 512);
#pragma unroll
                for (int j = 0; j < 8; j++) {
                    float2 v = __half22float2(tr[lane + 32 * j]);
                    float2 cv = *(const float2*)&usm[(lane + 32 * j) * 2];
                    dot += v.x * cv.x + v.y * cv.y;
                }
#pragma unroll
                for (int off = 16; off > 0; off >>= 1)
                    dot += __shfl_xor_sync(0xffffffffu, dot, off);
            }
            if (lane == 0) {
                size_t row = rowbase + st * RSTG + rl;
                float sq = g_norms[row] + g_norms[M_ROWS + row]
                         + g_norms[2 * M_ROWS + row] + g_norms[3 * M_ROWS + row];
                float scale = (sq / (1.f + sq)) * rsqrtf(sq + 1e-7f);
                float bv;
                if (do_dot) {
                    bv = g_b[row] + scale * (dot + bcs);
                    g_b[row] = bv;
                } else {
                    bv = 0.f;
                }
                bst[rl] = bv;
                sst[rl] = scale;
            }
        }
        __syncthreads();

        if (t < 32) {
            float v = bst[lane];
            float m = v;
#pragma unroll
            for (int off = 16; off > 0; off >>= 1)
                m = fmaxf(m, __shfl_xor_sync(0xffffffffu, m, off));
            float rm = runMs;
            float nm = fmaxf(rm, m);
            float w = __expf(v - nm);
            float zst = w;
#pragma unroll
            for (int off = 16; off > 0; off >>= 1)
                zst += __shfl_xor_sync(0xffffffffu, zst, off);
            float wsv = w * sst[lane];
            float wss = wsv;
#pragma unroll
            for (int off = 16; off > 0; off >>= 1)
                wss += __shfl_xor_sync(0xffffffffu, wss, off);
            wst[lane] = wsv;
            if (lane == 0) {
                float f = __expf(rm - nm);
                fsh = f;
                Zsh = Zsh * f + zst;
                Wsh = Wsh * f + wss;
                runMs = nm;
            }
        }
        __syncthreads();

        float f = fsh;
        ax *= f; ay *= f;
        const __half2* col = (const __half2*)(tile + 2 * t);
#pragma unroll
        for (int r = 0; r < RSTG; r++) {
            float w = wst[r];
            float2 v = __half22float2(col[r * 256]);
            ax += w * v.x;
            ay += w * v.y;
        }
    }

    int pc = c * NCHUNK + chunk;
    *(float2*)&g_Vp[(size_t)pc * 512 + 2 * t] = make_float2(ax, ay);
    if (t == 0) { g_Mp[pc] = runMs; g_Zp[pc] = Zsh; g_Wp[pc] = Wsh; }
}

// ============================================================================
// cmat (fused reduce): y from chunk partials; craw = y.W_o + bias_o*wts.
// ============================================================================
__global__ void __launch_bounds__(256) cmat_kernel(
    const float* __restrict__ W, const float* __restrict__ bias)
{
    const int ob = blockIdx.x, c = blockIdx.y;
    const int t = threadIdx.x, wid = t >> 5, lane = t & 31;
    __shared__ float ysm[512];
    __shared__ float sk[NCHUNK];
    __shared__ float ssp[8];
    __shared__ float Zs, Wts;

    if (t == 0) {
        float M = g_Mp[c * NCHUNK];
#pragma unroll
        for (int k = 1; k < NCHUNK; k++) M = fmaxf(M, g_Mp[c * NCHUNK + k]);
        float Z = 0.f, Wt = 0.f;
#pragma unroll
        for (int k = 0; k < NCHUNK; k++) {
            float e = __expf(g_Mp[c * NCHUNK + k] - M);
            sk[k] = e;
            Z  += g_Zp[c * NCHUNK + k] * e;
            Wt += g_Wp[c * NCHUNK + k] * e;
        }
        Zs = Z;
        Wts = Wt / Z;
    }
    __syncthreads();

    {
        float w0 = 0.f, w1 = 0.f;
#pragma unroll
        for (int k = 0; k < NCHUNK; k++) {
            float e = sk[k];
            float2 v = *(const float2*)&g_Vp[((size_t)(c * NCHUNK + k)) * 512 + 2 * t];
            w0 += e * v.x;
            w1 += e * v.y;
        }
        float invZ = 1.f / Zs;
        ysm[2 * t] = w0 * invZ;
        ysm[2 * t + 1] = w1 * invZ;
    }
    __syncthreads();

    const float Wts_l = Wts;
    float ss = 0.f;
#pragma unroll
    for (int i = 0; i < 8; i++) {
        int o = ob * 64 + wid * 8 + i;
        const float4* wr = (const float4*)(W + (size_t)o * 512);
        float d = 0.f;
#pragma unroll
        for (int g = 0; g < 4; g++) {
            float4 a = wr[lane + 32 * g];
            float4 b = *(const float4*)&ysm[(lane + 32 * g) * 4];
            d += a.x * b.x + a.y * b.y + a.z * b.z + a.w * b.w;
        }
#pragma unroll
        for (int off = 16; off > 0; off >>= 1)
            d += __shfl_xor_sync(0xffffffffu, d, off);
        if (lane == 0) {
            float cr = d + bias[o] * Wts_l;
            g_craw[c * 512 + o] = cr;
            ss += cr * cr;
        }
    }
    if (lane == 0) ssp[wid] = ss;
    __syncthreads();
    if (t == 0) {
        float s = 0.f;
#pragma unroll
        for (int k = 0; k < 8; k++) s += ssp[k];
        g_sqp[c * 8 + ob] = s;
    }
}

// ============================================================================
// ustep: scale; u = scale * W^T craw ; bc = scale*(bias.craw).
// ============================================================================
__global__ void __launch_bounds__(256) ustep_kernel(
    const float* __restrict__ W, const float* __restrict__ bias)
{
    const int ob = blockIdx.x, c = blockIdx.y;
    const int t = threadIdx.x;
    const int og = t >> 5, cp = t & 31;

    __shared__ float csm[512];
    __shared__ float2 up[8][32];
    __shared__ float scsh;
    __shared__ float red2[8];

    csm[t]       = g_craw[c * 512 + t];
    csm[t + 256] = g_craw[c * 512 + t + 256];
    if (t == 0) {
        float sq = 0.f;
#pragma unroll
        for (int k = 0; k < 8; k++) sq += g_sqp[c * 8 + k];
        scsh = (sq / (1.f + sq)) * rsqrtf(sq + 1e-7f);
    }
    __syncthreads();
    const float scale = scsh;

    float u0 = 0.f, u1 = 0.f;
    const float* wp = W + (size_t)(og * 64) * 512 + ob * 64 + cp * 2;
#pragma unroll 8
    for (int o = 0; o < 64; o++) {
        float co = csm[og * 64 + o];
        float2 wv = *(const float2*)(wp + (size_t)o * 512);
        u0 += co * wv.x;
        u1 += co * wv.y;
    }
    up[og][cp] = make_float2(u0, u1);
    __syncthreads();

    if (t < 32) {
        float sx = 0.f, sy = 0.f;
#pragma unroll
        for (int k = 0; k < 8; k++) { sx += up[k][t].x; sy += up[k][t].y; }
        *(float2*)&g_u[c * 512 + ob * 64 + t * 2] =
            make_float2(scale * sx, scale * sy);
    }

    if (ob == 0) {
        float p = bias[t] * csm[t] + bias[t + 256] * csm[t + 256];
#pragma unroll
        for (int off = 16; off > 0; off >>= 1)
            p += __shfl_xor_sync(0xffffffffu, p, off);
        if ((t & 31) == 0) red2[t >> 5] = p;
        __syncthreads();
        if (t == 0) {
            float pp = 0.f;
#pragma unroll
            for (int k = 0; k < 8; k++) pp += red2[k];
            g_bc[c] = scale * pp;
        }
    }
}

// ============================================================================
__global__ void __launch_bounds__(256) out_kernel(float* __restrict__ out) {
    const int c = blockIdx.x, t = threadIdx.x;
    __shared__ float scsh;
    if (t == 0) {
        float sq = 0.f;
#pragma unroll
        for (int k = 0; k < 8; k++) sq += g_sqp[c * 8 + k];
        scsh = (sq / (1.f + sq)) * rsqrtf(sq + 1e-7f);
    }
    __syncthreads();
    out[c * 512 + t]       = scsh * g_craw[c * 512 + t];
    out[c * 512 + t + 256] = scsh * g_craw[c * 512 + t + 256];
}

// ============================================================================
extern "C" void kernel_launch(void* const* d_in, const int* in_sizes, int n_in,
                              void* d_out, int out_size) {
    const float* x    = (const float*)d_in[0];
    const float* W    = (const float*)d_in[1];
    const float* bias = (const float*)d_in[2];
    float* out = (float*)d_out;

    void* pb = nullptr; cudaGetSymbolAddress(&pb, g_b);
    cudaMemsetAsync(pb, 0, (size_t)M_ROWS * sizeof(float));

    convw_kernel<<<256, 256>>>(W);

    static bool attr_done = false;
    if (!attr_done) {
        cudaFuncSetAttribute(gemm_norms, cudaFuncAttributeMaxDynamicSharedMemorySize, GSM_TOTAL);
        cudaFuncSetAttribute(sweep_pass, cudaFuncAttributeMaxDynamicSharedMemorySize, SWEEP_SMEM);
        attr_done = true;
    }
    gemm_norms<<<dim3(4, 1024), 256, GSM_TOTAL>>>(x, bias);

    for (int it = 0; it < 3; ++it) {
        sweep_pass<<<dim3(NCHUNK, C_CAPS), 256, SWEEP_SMEM>>>(it > 0 ? 1 : 0);
        cmat_kernel<<<dim3(8, C_CAPS), 256>>>(W, bias);
        if (it < 2) ustep_kernel<<<dim3(8, C_CAPS), 256>>>(W, bias);
        else        out_kernel<<<C_CAPS, 256>>>(out);
    }
}

// round 14
// speedup vs baseline: 1.2892x; 1.2087x over previous
#include <cuda_runtime.h>
#include <cuda_fp16.h>
#include <cstdint>

#define C_CAPS 64
#define S_DIM 2048
#define H_DIM 512
#define M_ROWS (C_CAPS * S_DIM)   // 131072
#define NCHUNK 16
#define CHUNK_S (S_DIM / NCHUNK)  // 128
#define RSTG 32
#define NSTG (CHUNK_S / RSTG)     // 4
#define SLOTS 3

// ---------------- device scratch ----------------
__device__ __align__(128) __half g_whf[(size_t)H_DIM * H_DIM];   // pre-swizzled fp16 W
__device__ __align__(128) __half g_xhf[(size_t)M_ROWS * H_DIM];  // linear fp16 x
__device__ float g_norms[2 * M_ROWS];     // 2 n-halves now (CTA covers 256 cols)
__device__ float g_scale[M_ROWS];
__device__ float g_b[M_ROWS];
__device__ float g_u[C_CAPS * H_DIM];
__device__ float g_bc[C_CAPS];
__device__ float g_Mp[C_CAPS * NCHUNK];
__device__ float g_Zp[C_CAPS * NCHUNK];
__device__ float g_Wp[C_CAPS * NCHUNK];
__device__ float g_Vp[(size_t)C_CAPS * NCHUNK * H_DIM];
__device__ float g_craw[C_CAPS * H_DIM];
__device__ float g_sqp[C_CAPS * 8];

// ---------------- helpers ----------------
__device__ __forceinline__ uint32_t smem_u32(const void* p) {
    uint32_t a;
    asm("{ .reg .u64 t; cvta.to.shared.u64 t, %1; cvt.u32.u64 %0, t; }" : "=r"(a) : "l"(p));
    return a;
}
__device__ __forceinline__ void ldsm4(uint32_t* r, uint32_t addr) {
    asm volatile("ldmatrix.sync.aligned.m8n8.x4.shared.b16 {%0,%1,%2,%3}, [%4];"
        : "=r"(r[0]), "=r"(r[1]), "=r"(r[2]), "=r"(r[3]) : "r"(addr));
}
__device__ __forceinline__ void mma16816h(uint32_t* d, const uint32_t* a, const uint32_t* b) {
    asm volatile("mma.sync.aligned.m16n8k16.row.col.f16.f16.f16.f16 "
        "{%0,%1}, {%2,%3,%4,%5}, {%6,%7}, {%0,%1};"
        : "+r"(d[0]), "+r"(d[1])
        : "r"(a[0]), "r"(a[1]), "r"(a[2]), "r"(a[3]), "r"(b[0]), "r"(b[1]));
}
__device__ __forceinline__ void sts128(uint32_t addr, uint4 v) {
    asm volatile("st.shared.v4.b32 [%0], {%1,%2,%3,%4};"
        :: "r"(addr), "r"(v.x), "r"(v.y), "r"(v.z), "r"(v.w) : "memory");
}
#define CP_ASYNC16(dst, src) \
    asm volatile("cp.async.cg.shared.global [%0], [%1], 16;" :: "r"(dst), "l"(src) : "memory")
#define CP_COMMIT() asm volatile("cp.async.commit_group;" ::: "memory")
#define CP_WAIT(n)  asm volatile("cp.async.wait_group %0;" :: "n"(n) : "memory")

__device__ __forceinline__ uint32_t packh2(float x, float y) {
    __half2 h = __floats2half2_rn(x, y);
    return *(uint32_t*)&h;
}
__device__ __forceinline__ uint32_t tswz(uint32_t row, uint32_t kc) {
    return row * 64u + ((kc ^ ((row >> 1) & 3u)) << 4);
}

// ============================================================================
// convw: W fp32 -> pre-swizzled fp16 tiles (8KB blocks [128 rows x 32 k]).
// ============================================================================
__global__ void convw_kernel(const float* __restrict__ W) {
    int g = blockIdx.x * 256 + threadIdx.x;
    int n = g >> 7, ch = g & 127;
    int kt = ch >> 3, kc = (ch >> 1) & 3, half = ch & 1;
    int bn = n >> 7, nrow = n & 127;
    float4 v = *(const float4*)&W[(size_t)n * 512 + ch * 4];
    uint2 hi;
    hi.x = packh2(v.x, v.y);
    hi.y = packh2(v.z, v.w);
    size_t dst = ((size_t)(bn * 16 + kt) << 13) + tswz(nrow, kc) + half * 8;
    *(uint2*)((char*)g_whf + dst) = hi;
}

// ============================================================================
// GEMM (norms only): CTA 128x256, warp tile 64x64 (2x4 warps), BK=32, fp16
// f16-acc HMMA. Stage = A 8K | B0 8K | B1 8K, double-buffered.
// bn==0 blocks export fp16 x to g_xhf.
// ============================================================================
#define GSM_STAGE 24576
#define GSM_TOTAL (2 * GSM_STAGE + 512)

__device__ __forceinline__ void issueB(uint32_t stg, int bn, int kt, int t) {
    size_t t0 = (size_t)((bn * 2) * 16 + kt) << 13;
    size_t t1 = (size_t)((bn * 2 + 1) * 16 + kt) << 13;
    const char* s0 = (const char*)g_whf + t0 + t * 32;
    const char* s1 = (const char*)g_whf + t1 + t * 32;
    CP_ASYNC16(stg + 8192 + t * 32, s0);
    CP_ASYNC16(stg + 8192 + t * 32 + 16, s0 + 16);
    CP_ASYNC16(stg + 16384 + t * 32, s1);
    CP_ASYNC16(stg + 16384 + t * 32 + 16, s1 + 16);
}

__global__ void __launch_bounds__(256, 2) gemm_norms(
    const float* __restrict__ x, const float* __restrict__ bias)
{
    extern __shared__ __align__(1024) char smem[];
    const uint32_t sb = smem_u32(smem);

    const int t = threadIdx.x, l = t & 31, wid = t >> 5;
    const int wm = wid & 1, wn = wid >> 1;   // 2 m-strips x 4 n-strips of 64
    const int bn = blockIdx.x, mtile = blockIdx.y;

    const int c0row = t >> 2, ckc = t & 3;
    const float* ag0 = x + ((size_t)mtile * 128 + c0row) * 512 + ckc * 8;
    const float* ag1 = x + ((size_t)mtile * 128 + c0row + 64) * 512 + ckc * 8;
    const uint32_t so0 = tswz(c0row, ckc);
    const uint32_t so1 = tswz(c0row + 64, ckc);

    __half* xo0 = g_xhf + ((size_t)mtile * 128 + c0row) * 512 + ckc * 8;
    __half* xo1 = g_xhf + ((size_t)mtile * 128 + c0row + 64) * 512 + ckc * 8;

    uint32_t aoffA[4][2], aoffB[4][2];
#pragma unroll
    for (int mt = 0; mt < 4; mt++)
#pragma unroll
        for (int ks = 0; ks < 2; ks++) {
            uint32_t m = wm * 64 + mt * 16 + ((l >> 3) & 1) * 8 + (l & 7);
            aoffA[mt][ks] = tswz(m, ks * 2 + (l >> 4));
        }
#pragma unroll
    for (int nt2 = 0; nt2 < 4; nt2++)
#pragma unroll
        for (int ks = 0; ks < 2; ks++) {
            uint32_t n = wn * 64 + nt2 * 16 + ((l >> 4) & 1) * 8 + (l & 7);
            uint32_t blk = n >> 7;
            aoffB[nt2][ks] = 8192 + blk * 8192 + tswz(n & 127, ks * 2 + ((l >> 3) & 1));
        }

    uint32_t acc[4][8][2];
#pragma unroll
    for (int mt = 0; mt < 4; mt++)
#pragma unroll
        for (int nt = 0; nt < 8; nt++) { acc[mt][nt][0] = 0u; acc[mt][nt][1] = 0u; }

    issueB(sb, bn, 0, t);
    CP_COMMIT();
    // A prefetch (packed fp16, 8 regs)
    uint4 ha0, ha1;
    {
        float4 p0 = *(const float4*)(ag0), p1 = *(const float4*)(ag0 + 4);
        float4 p2 = *(const float4*)(ag1), p3 = *(const float4*)(ag1 + 4);
        ha0.x = packh2(p0.x, p0.y); ha0.y = packh2(p0.z, p0.w);
        ha0.z = packh2(p1.x, p1.y); ha0.w = packh2(p1.z, p1.w);
        ha1.x = packh2(p2.x, p2.y); ha1.y = packh2(p2.z, p2.w);
        ha1.z = packh2(p3.x, p3.y); ha1.w = packh2(p3.z, p3.w);
    }

    for (int kt = 0; kt < 16; kt++) {
        const uint32_t stg = sb + (kt & 1) * GSM_STAGE;
        sts128(stg + so0, ha0);
        sts128(stg + so1, ha1);
        if (bn == 0) {
            *(uint4*)(xo0 + kt * 32) = ha0;
            *(uint4*)(xo1 + kt * 32) = ha1;
        }
        if (kt < 15) {
            issueB(sb + ((kt + 1) & 1) * GSM_STAGE, bn, kt + 1, t);
            CP_COMMIT();
            CP_WAIT(1);
        } else {
            CP_WAIT(0);
        }
        __syncthreads();

        if (kt < 15) {
            int ko = (kt + 1) * 32;
            float4 p0 = *(const float4*)(ag0 + ko), p1 = *(const float4*)(ag0 + ko + 4);
            float4 p2 = *(const float4*)(ag1 + ko), p3 = *(const float4*)(ag1 + ko + 4);
            ha0.x = packh2(p0.x, p0.y); ha0.y = packh2(p0.z, p0.w);
            ha0.z = packh2(p1.x, p1.y); ha0.w = packh2(p1.z, p1.w);
            ha1.x = packh2(p2.x, p2.y); ha1.y = packh2(p2.z, p2.w);
            ha1.z = packh2(p3.x, p3.y); ha1.w = packh2(p3.z, p3.w);
        }

#pragma unroll
        for (int ks = 0; ks < 2; ks++) {
            uint32_t ah[4][4], bh[4][4];
#pragma unroll
            for (int mt = 0; mt < 4; mt++) ldsm4(ah[mt], stg + aoffA[mt][ks]);
#pragma unroll
            for (int nt2 = 0; nt2 < 4; nt2++) ldsm4(bh[nt2], stg + aoffB[nt2][ks]);
#pragma unroll
            for (int mt = 0; mt < 4; mt++)
#pragma unroll
                for (int nt = 0; nt < 8; nt++)
                    mma16816h(acc[mt][nt], ah[mt], &bh[nt >> 1][(nt & 1) * 2]);
        }
        __syncthreads();
    }

    // ---- epilogue: bias add + row-norm partials ----
    float* norm_sm = (float*)(smem + 2 * GSM_STAGE);
    if (t < 128) norm_sm[t] = 0.f;
    __syncthreads();

    float2 bias2[8];
#pragma unroll
    for (int nt = 0; nt < 8; nt++)
        bias2[nt] = *(const float2*)&bias[bn * 256 + wn * 64 + nt * 8 + (l & 3) * 2];

#pragma unroll
    for (int mt = 0; mt < 4; mt++)
#pragma unroll
        for (int half = 0; half < 2; half++) {
            int r = wm * 64 + mt * 16 + (l >> 2) + half * 8;
            float ss = 0.f;
#pragma unroll
            for (int nt = 0; nt < 8; nt++) {
                float2 v = __half22float2(*(__half2*)&acc[mt][nt][half]);
                float vx = v.x + bias2[nt].x;
                float vy = v.y + bias2[nt].y;
                ss += vx * vx + vy * vy;
            }
            ss += __shfl_xor_sync(0xffffffffu, ss, 1);
            ss += __shfl_xor_sync(0xffffffffu, ss, 2);
            if ((l & 3) == 0) atomicAdd(&norm_sm[r], ss);
        }
    __syncthreads();
    if (t < 128)
        g_norms[(size_t)bn * M_ROWS + (size_t)mtile * 128 + t] = norm_sm[t];
}

// ============================================================================
// pass0: iteration 0 has uniform softmax (b == 0). Compute scales (store
// g_scale), y0 partials = sum_s scale_s * x_s, Wp = sum scale. No softmax.
// grid (16, 64), 256 threads.
// ============================================================================
__global__ void __launch_bounds__(256) pass0_kernel() {
    const int c = blockIdx.y, chunk = blockIdx.x;
    const int t = threadIdx.x, wid = t >> 5, lane = t & 31;
    __shared__ float ssc[CHUNK_S];
    __shared__ float wred[4];

    const size_t rowbase = (size_t)c * S_DIM + (size_t)chunk * CHUNK_S;
    if (t < CHUNK_S) {
        size_t row = rowbase + t;
        float sq = g_norms[row] + g_norms[M_ROWS + row];
        float s = (sq / (1.f + sq)) * rsqrtf(sq + 1e-7f);
        ssc[t] = s;
        g_scale[row] = s;
    }
    __syncthreads();

    float ax = 0.f, ay = 0.f;
    const __half2* xp = (const __half2*)(g_xhf + rowbase * 512) + t;
#pragma unroll 4
    for (int s = 0; s < CHUNK_S; s++) {
        float2 v = __half22float2(xp[s * 256]);
        float w = ssc[s];
        ax += w * v.x;
        ay += w * v.y;
    }
    int pc = c * NCHUNK + chunk;
    *(float2*)&g_Vp[(size_t)pc * 512 + 2 * t] = make_float2(ax, ay);

    if (t < CHUNK_S) {
        float p = ssc[t];
#pragma unroll
        for (int off = 16; off > 0; off >>= 1)
            p += __shfl_xor_sync(0xffffffffu, p, off);
        if (lane == 0) wred[wid] = p;
    }
    __syncthreads();
    if (t == 0) {
        g_Mp[pc] = 0.f;
        g_Zp[pc] = (float)CHUNK_S;
        g_Wp[pc] = wred[0] + wred[1] + wred[2] + wred[3];
    }
}

// ============================================================================
// Sweep (iterations 1,2): fp16 x, 3-slot cp.async ring, 32-row stages.
// first==1: b_prev = 0 (not read).
// ============================================================================
#define SWEEP_SMEM (SLOTS * RSTG * 512 * 2)

__device__ __forceinline__ void sweep_issue(const __half* src, __half* slot, int t) {
    uint32_t dst = smem_u32(slot);
    const char* s = (const char*)src;
#pragma unroll
    for (int i = 0; i < 8; i++) {
        int idx = t + 256 * i;
        CP_ASYNC16(dst + idx * 16, s + idx * 16);
    }
    CP_COMMIT();
}

__global__ void __launch_bounds__(256, 2) sweep_pass(int first) {
    extern __shared__ __align__(16) __half tiles[];
    __shared__ float usm[512];
    __shared__ float bst[RSTG], wst[RSTG];
    __shared__ float runMs, Zsh, Wsh, fsh, bcs;

    const int c = blockIdx.y, chunk = blockIdx.x;
    const int t = threadIdx.x, wid = t >> 5, lane = t & 31;

    usm[t]       = g_u[c * 512 + t];
    usm[t + 256] = g_u[c * 512 + t + 256];
    if (t == 0) { runMs = -1e30f; Zsh = 0.f; Wsh = 0.f; bcs = g_bc[c]; }

    const size_t rowbase = (size_t)c * S_DIM + (size_t)chunk * CHUNK_S;
    const __half* xsrc = g_xhf + rowbase * 512;
    float ax = 0.f, ay = 0.f;

    sweep_issue(xsrc, tiles, t);
    sweep_issue(xsrc + (size_t)RSTG * 512, tiles + RSTG * 512, t);

    for (int st = 0; st < NSTG; st++) {
        if (st < NSTG - 1) { CP_WAIT(1); } else { CP_WAIT(0); }
        __syncthreads();
        __half* tile = tiles + (st % SLOTS) * (RSTG * 512);

        if (st + 2 < NSTG)
            sweep_issue(xsrc + (size_t)(st + 2) * RSTG * 512,
                        tiles + ((st + 2) % SLOTS) * (RSTG * 512), t);

#pragma unroll
        for (int rr = 0; rr < 4; rr++) {
            int rl = wid * 4 + rr;
            const __half2* tr = (const __half2*)(tile + rl * 512);
            float dot = 0.f;
#pragma unroll
            for (int j = 0; j < 8; j++) {
                float2 v = __half22float2(tr[lane + 32 * j]);
                float2 cv = *(const float2*)&usm[(lane + 32 * j) * 2];
                dot += v.x * cv.x + v.y * cv.y;
            }
#pragma unroll
            for (int off = 16; off > 0; off >>= 1)
                dot += __shfl_xor_sync(0xffffffffu, dot, off);
            if (lane == 0) {
                size_t row = rowbase + st * RSTG + rl;
                float scale = g_scale[row];
                float bv = scale * (dot + bcs);
                if (!first) bv += g_b[row];
                g_b[row] = bv;
                bst[rl] = bv;
                wst[rl] = scale;   // temporarily hold scale
            }
        }
        __syncthreads();

        if (t < 32) {
            float v = bst[lane];
            float sc = wst[lane];
            float m = v;
#pragma unroll
            for (int off = 16; off > 0; off >>= 1)
                m = fmaxf(m, __shfl_xor_sync(0xffffffffu, m, off));
            float rm = runMs;
            float nm = fmaxf(rm, m);
            float w = __expf(v - nm);
            float zst = w;
#pragma unroll
            for (int off = 16; off > 0; off >>= 1)
                zst += __shfl_xor_sync(0xffffffffu, zst, off);
            float wsv = w * sc;
            float wss = wsv;
#pragma unroll
            for (int off = 16; off > 0; off >>= 1)
                wss += __shfl_xor_sync(0xffffffffu, wss, off);
            wst[lane] = wsv;
            if (lane == 0) {
                float f = __expf(rm - nm);
                fsh = f;
                Zsh = Zsh * f + zst;
                Wsh = Wsh * f + wss;
                runMs = nm;
            }
        }
        __syncthreads();

        float f = fsh;
        ax *= f; ay *= f;
        const __half2* col = (const __half2*)(tile + 2 * t);
#pragma unroll
        for (int r = 0; r < RSTG; r++) {
            float w = wst[r];
            float2 v = __half22float2(col[r * 256]);
            ax += w * v.x;
            ay += w * v.y;
        }
    }

    int pc = c * NCHUNK + chunk;
    *(float2*)&g_Vp[(size_t)pc * 512 + 2 * t] = make_float2(ax, ay);
    if (t == 0) { g_Mp[pc] = runMs; g_Zp[pc] = Zsh; g_Wp[pc] = Wsh; }
}

// ============================================================================
// cmat (fused reduce): y from chunk partials; craw = y.W_o + bias_o*wts.
// ============================================================================
__global__ void __launch_bounds__(256) cmat_kernel(
    const float* __restrict__ W, const float* __restrict__ bias)
{
    const int ob = blockIdx.x, c = blockIdx.y;
    const int t = threadIdx.x, wid = t >> 5, lane = t & 31;
    __shared__ float ysm[512];
    __shared__ float sk[NCHUNK];
    __shared__ float ssp[8];
    __shared__ float Zs, Wts;

    if (t == 0) {
        float M = g_Mp[c * NCHUNK];
#pragma unroll
        for (int k = 1; k < NCHUNK; k++) M = fmaxf(M, g_Mp[c * NCHUNK + k]);
        float Z = 0.f, Wt = 0.f;
#pragma unroll
        for (int k = 0; k < NCHUNK; k++) {
            float e = __expf(g_Mp[c * NCHUNK + k] - M);
            sk[k] = e;
            Z  += g_Zp[c * NCHUNK + k] * e;
            Wt += g_Wp[c * NCHUNK + k] * e;
        }
        Zs = Z;
        Wts = Wt / Z;
    }
    __syncthreads();

    {
        float w0 = 0.f, w1 = 0.f;
#pragma unroll
        for (int k = 0; k < NCHUNK; k++) {
            float e = sk[k];
            float2 v = *(const float2*)&g_Vp[((size_t)(c * NCHUNK + k)) * 512 + 2 * t];
            w0 += e * v.x;
            w1 += e * v.y;
        }
        float invZ = 1.f / Zs;
        ysm[2 * t] = w0 * invZ;
        ysm[2 * t + 1] = w1 * invZ;
    }
    __syncthreads();

    const float Wts_l = Wts;
    float ss = 0.f;
#pragma unroll
    for (int i = 0; i < 8; i++) {
        int o = ob * 64 + wid * 8 + i;
        const float4* wr = (const float4*)(W + (size_t)o * 512);
        float d = 0.f;
#pragma unroll
        for (int g = 0; g < 4; g++) {
            float4 a = wr[lane + 32 * g];
            float4 b = *(const float4*)&ysm[(lane + 32 * g) * 4];
            d += a.x * b.x + a.y * b.y + a.z * b.z + a.w * b.w;
        }
#pragma unroll
        for (int off = 16; off > 0; off >>= 1)
            d += __shfl_xor_sync(0xffffffffu, d, off);
        if (lane == 0) {
            float cr = d + bias[o] * Wts_l;
            g_craw[c * 512 + o] = cr;
            ss += cr * cr;
        }
    }
    if (lane == 0) ssp[wid] = ss;
    __syncthreads();
    if (t == 0) {
        float s = 0.f;
#pragma unroll
        for (int k = 0; k < 8; k++) s += ssp[k];
        g_sqp[c * 8 + ob] = s;
    }
}

// ============================================================================
// ustep: scale; u = scale * W^T craw ; bc = scale*(bias.craw).
// ============================================================================
__global__ void __launch_bounds__(256) ustep_kernel(
    const float* __restrict__ W, const float* __restrict__ bias)
{
    const int ob = blockIdx.x, c = blockIdx.y;
    const int t = threadIdx.x;
    const int og = t >> 5, cp = t & 31;

    __shared__ float csm[512];
    __shared__ float2 up[8][32];
    __shared__ float scsh;
    __shared__ float red2[8];

    csm[t]       = g_craw[c * 512 + t];
    csm[t + 256] = g_craw[c * 512 + t + 256];
    if (t == 0) {
        float sq = 0.f;
#pragma unroll
        for (int k = 0; k < 8; k++) sq += g_sqp[c * 8 + k];
        scsh = (sq / (1.f + sq)) * rsqrtf(sq + 1e-7f);
    }
    __syncthreads();
    const float scale = scsh;

    float u0 = 0.f, u1 = 0.f;
    const float* wp = W + (size_t)(og * 64) * 512 + ob * 64 + cp * 2;
#pragma unroll 8
    for (int o = 0; o < 64; o++) {
        float co = csm[og * 64 + o];
        float2 wv = *(const float2*)(wp + (size_t)o * 512);
        u0 += co * wv.x;
        u1 += co * wv.y;
    }
    up[og][cp] = make_float2(u0, u1);
    __syncthreads();

    if (t < 32) {
        float sx = 0.f, sy = 0.f;
#pragma unroll
        for (int k = 0; k < 8; k++) { sx += up[k][t].x; sy += up[k][t].y; }
        *(float2*)&g_u[c * 512 + ob * 64 + t * 2] =
            make_float2(scale * sx, scale * sy);
    }

    if (ob == 0) {
        float p = bias[t] * csm[t] + bias[t + 256] * csm[t + 256];
#pragma unroll
        for (int off = 16; off > 0; off >>= 1)
            p += __shfl_xor_sync(0xffffffffu, p, off);
        if ((t & 31) == 0) red2[t >> 5] = p;
        __syncthreads();
        if (t == 0) {
            float pp = 0.f;
#pragma unroll
            for (int k = 0; k < 8; k++) pp += red2[k];
            g_bc[c] = scale * pp;
        }
    }
}

// ============================================================================
__global__ void __launch_bounds__(256) out_kernel(float* __restrict__ out) {
    const int c = blockIdx.x, t = threadIdx.x;
    __shared__ float scsh;
    if (t == 0) {
        float sq = 0.f;
#pragma unroll
        for (int k = 0; k < 8; k++) sq += g_sqp[c * 8 + k];
        scsh = (sq / (1.f + sq)) * rsqrtf(sq + 1e-7f);
    }
    __syncthreads();
    out[c * 512 + t]       = scsh * g_craw[c * 512 + t];
    out[c * 512 + t + 256] = scsh * g_craw[c * 512 + t + 256];
}

// ============================================================================
extern "C" void kernel_launch(void* const* d_in, const int* in_sizes, int n_in,
                              void* d_out, int out_size) {
    const float* x    = (const float*)d_in[0];
    const float* W    = (const float*)d_in[1];
    const float* bias = (const float*)d_in[2];
    float* out = (float*)d_out;

    convw_kernel<<<256, 256>>>(W);

    static bool attr_done = false;
    if (!attr_done) {
        cudaFuncSetAttribute(gemm_norms, cudaFuncAttributeMaxDynamicSharedMemorySize, GSM_TOTAL);
        cudaFuncSetAttribute(sweep_pass, cudaFuncAttributeMaxDynamicSharedMemorySize, SWEEP_SMEM);
        attr_done = true;
    }
    gemm_norms<<<dim3(2, 1024), 256, GSM_TOTAL>>>(x, bias);

    // iteration 0 (uniform softmax)
    pass0_kernel<<<dim3(NCHUNK, C_CAPS), 256>>>();
    cmat_kernel<<<dim3(8, C_CAPS), 256>>>(W, bias);
    ustep_kernel<<<dim3(8, C_CAPS), 256>>>(W, bias);

    // iteration 1
    sweep_pass<<<dim3(NCHUNK, C_CAPS), 256, SWEEP_SMEM>>>(1);
    cmat_kernel<<<dim3(8, C_CAPS), 256>>>(W, bias);
    ustep_kernel<<<dim3(8, C_CAPS), 256>>>(W, bias);

    // iteration 2
    sweep_pass<<<dim3(NCHUNK, C_CAPS), 256, SWEEP_SMEM>>>(0);
    cmat_kernel<<<dim3(8, C_CAPS), 256>>>(W, bias);
    out_kernel<<<C_CAPS, 256>>>(out);
}

// round 15
// speedup vs baseline: 1.2921x; 1.0022x over previous
#include <cuda_runtime.h>
#include <cuda_fp16.h>
#include <cstdint>

#define C_CAPS 64
#define S_DIM 2048
#define H_DIM 512
#define M_ROWS (C_CAPS * S_DIM)   // 131072
#define NCHUNK 16
#define CHUNK_S (S_DIM / NCHUNK)  // 128
#define RSTG 32
#define NSTG (CHUNK_S / RSTG)     // 4
#define SLOTS 3

// ---------------- device scratch ----------------
__device__ __align__(128) __half g_whf[(size_t)H_DIM * H_DIM];   // pre-swizzled fp16 W
__device__ __align__(128) __half g_xhf[(size_t)M_ROWS * H_DIM];  // linear fp16 x
__device__ float g_norms[2 * M_ROWS];
__device__ float g_scale[M_ROWS];
__device__ float g_b[M_ROWS];
__device__ float g_u[C_CAPS * H_DIM];      // UNSCALED W^T craw (atomic-accumulated)
__device__ float g_bc[C_CAPS];             // UNSCALED bias.craw
__device__ float g_Mp[C_CAPS * NCHUNK];
__device__ float g_Zp[C_CAPS * NCHUNK];
__device__ float g_Wp[C_CAPS * NCHUNK];
__device__ float g_Vp[(size_t)C_CAPS * NCHUNK * H_DIM];
__device__ float g_craw[C_CAPS * H_DIM];
__device__ float g_sqp[C_CAPS * 8];

// ---------------- helpers ----------------
__device__ __forceinline__ uint32_t smem_u32(const void* p) {
    uint32_t a;
    asm("{ .reg .u64 t; cvta.to.shared.u64 t, %1; cvt.u32.u64 %0, t; }" : "=r"(a) : "l"(p));
    return a;
}
__device__ __forceinline__ void ldsm4(uint32_t* r, uint32_t addr) {
    asm volatile("ldmatrix.sync.aligned.m8n8.x4.shared.b16 {%0,%1,%2,%3}, [%4];"
        : "=r"(r[0]), "=r"(r[1]), "=r"(r[2]), "=r"(r[3]) : "r"(addr));
}
__device__ __forceinline__ void mma16816h(uint32_t* d, const uint32_t* a, const uint32_t* b) {
    asm volatile("mma.sync.aligned.m16n8k16.row.col.f16.f16.f16.f16 "
        "{%0,%1}, {%2,%3,%4,%5}, {%6,%7}, {%0,%1};"
        : "+r"(d[0]), "+r"(d[1])
        : "r"(a[0]), "r"(a[1]), "r"(a[2]), "r"(a[3]), "r"(b[0]), "r"(b[1]));
}
__device__ __forceinline__ void sts128(uint32_t addr, uint4 v) {
    asm volatile("st.shared.v4.b32 [%0], {%1,%2,%3,%4};"
        :: "r"(addr), "r"(v.x), "r"(v.y), "r"(v.z), "r"(v.w) : "memory");
}
#define CP_ASYNC16(dst, src) \
    asm volatile("cp.async.cg.shared.global [%0], [%1], 16;" :: "r"(dst), "l"(src) : "memory")
#define CP_COMMIT() asm volatile("cp.async.commit_group;" ::: "memory")
#define CP_WAIT(n)  asm volatile("cp.async.wait_group %0;" :: "n"(n) : "memory")

__device__ __forceinline__ uint32_t packh2(float x, float y) {
    __half2 h = __floats2half2_rn(x, y);
    return *(uint32_t*)&h;
}
__device__ __forceinline__ uint32_t tswz(uint32_t row, uint32_t kc) {
    return row * 64u + ((kc ^ ((row >> 1) & 3u)) << 4);
}

// ============================================================================
// convw: W fp32 -> pre-swizzled fp16 tiles (8KB blocks [128 rows x 32 k]).
// ============================================================================
__global__ void convw_kernel(const float* __restrict__ W) {
    int g = blockIdx.x * 256 + threadIdx.x;
    int n = g >> 7, ch = g & 127;
    int kt = ch >> 3, kc = (ch >> 1) & 3, half = ch & 1;
    int bn = n >> 7, nrow = n & 127;
    float4 v = *(const float4*)&W[(size_t)n * 512 + ch * 4];
    uint2 hi;
    hi.x = packh2(v.x, v.y);
    hi.y = packh2(v.z, v.w);
    size_t dst = ((size_t)(bn * 16 + kt) << 13) + tswz(nrow, kc) + half * 8;
    *(uint2*)((char*)g_whf + dst) = hi;
}

// ============================================================================
// GEMM (norms only): CTA 128x256, warp tile 64x64, BK=32, f16-acc HMMA.
// bn==0 blocks export fp16 x to g_xhf.
// ============================================================================
#define GSM_STAGE 24576
#define GSM_TOTAL (2 * GSM_STAGE + 512)

__device__ __forceinline__ void issueB(uint32_t stg, int bn, int kt, int t) {
    size_t t0 = (size_t)((bn * 2) * 16 + kt) << 13;
    size_t t1 = (size_t)((bn * 2 + 1) * 16 + kt) << 13;
    const char* s0 = (const char*)g_whf + t0 + t * 32;
    const char* s1 = (const char*)g_whf + t1 + t * 32;
    CP_ASYNC16(stg + 8192 + t * 32, s0);
    CP_ASYNC16(stg + 8192 + t * 32 + 16, s0 + 16);
    CP_ASYNC16(stg + 16384 + t * 32, s1);
    CP_ASYNC16(stg + 16384 + t * 32 + 16, s1 + 16);
}

__global__ void __launch_bounds__(256, 2) gemm_norms(
    const float* __restrict__ x, const float* __restrict__ bias)
{
    extern __shared__ __align__(1024) char smem[];
    const uint32_t sb = smem_u32(smem);

    const int t = threadIdx.x, l = t & 31, wid = t >> 5;
    const int wm = wid & 1, wn = wid >> 1;
    const int bn = blockIdx.x, mtile = blockIdx.y;

    const int c0row = t >> 2, ckc = t & 3;
    const float* ag0 = x + ((size_t)mtile * 128 + c0row) * 512 + ckc * 8;
    const float* ag1 = x + ((size_t)mtile * 128 + c0row + 64) * 512 + ckc * 8;
    const uint32_t so0 = tswz(c0row, ckc);
    const uint32_t so1 = tswz(c0row + 64, ckc);

    __half* xo0 = g_xhf + ((size_t)mtile * 128 + c0row) * 512 + ckc * 8;
    __half* xo1 = g_xhf + ((size_t)mtile * 128 + c0row + 64) * 512 + ckc * 8;

    uint32_t aoffA[4][2], aoffB[4][2];
#pragma unroll
    for (int mt = 0; mt < 4; mt++)
#pragma unroll
        for (int ks = 0; ks < 2; ks++) {
            uint32_t m = wm * 64 + mt * 16 + ((l >> 3) & 1) * 8 + (l & 7);
            aoffA[mt][ks] = tswz(m, ks * 2 + (l >> 4));
        }
#pragma unroll
    for (int nt2 = 0; nt2 < 4; nt2++)
#pragma unroll
        for (int ks = 0; ks < 2; ks++) {
            uint32_t n = wn * 64 + nt2 * 16 + ((l >> 4) & 1) * 8 + (l & 7);
            uint32_t blk = n >> 7;
            aoffB[nt2][ks] = 8192 + blk * 8192 + tswz(n & 127, ks * 2 + ((l >> 3) & 1));
        }

    uint32_t acc[4][8][2];
#pragma unroll
    for (int mt = 0; mt < 4; mt++)
#pragma unroll
        for (int nt = 0; nt < 8; nt++) { acc[mt][nt][0] = 0u; acc[mt][nt][1] = 0u; }

    issueB(sb, bn, 0, t);
    CP_COMMIT();
    uint4 ha0, ha1;
    {
        float4 p0 = *(const float4*)(ag0), p1 = *(const float4*)(ag0 + 4);
        float4 p2 = *(const float4*)(ag1), p3 = *(const float4*)(ag1 + 4);
        ha0.x = packh2(p0.x, p0.y); ha0.y = packh2(p0.z, p0.w);
        ha0.z = packh2(p1.x, p1.y); ha0.w = packh2(p1.z, p1.w);
        ha1.x = packh2(p2.x, p2.y); ha1.y = packh2(p2.z, p2.w);
        ha1.z = packh2(p3.x, p3.y); ha1.w = packh2(p3.z, p3.w);
    }

    for (int kt = 0; kt < 16; kt++) {
        const uint32_t stg = sb + (kt & 1) * GSM_STAGE;
        sts128(stg + so0, ha0);
        sts128(stg + so1, ha1);
        if (bn == 0) {
            *(uint4*)(xo0 + kt * 32) = ha0;
            *(uint4*)(xo1 + kt * 32) = ha1;
        }
        if (kt < 15) {
            issueB(sb + ((kt + 1) & 1) * GSM_STAGE, bn, kt + 1, t);
            CP_COMMIT();
            CP_WAIT(1);
        } else {
            CP_WAIT(0);
        }
        __syncthreads();

        if (kt < 15) {
            int ko = (kt + 1) * 32;
            float4 p0 = *(const float4*)(ag0 + ko), p1 = *(const float4*)(ag0 + ko + 4);
            float4 p2 = *(const float4*)(ag1 + ko), p3 = *(const float4*)(ag1 + ko + 4);
            ha0.x = packh2(p0.x, p0.y); ha0.y = packh2(p0.z, p0.w);
            ha0.z = packh2(p1.x, p1.y); ha0.w = packh2(p1.z, p1.w);
            ha1.x = packh2(p2.x, p2.y); ha1.y = packh2(p2.z, p2.w);
            ha1.z = packh2(p3.x, p3.y); ha1.w = packh2(p3.z, p3.w);
        }

#pragma unroll
        for (int ks = 0; ks < 2; ks++) {
            uint32_t ah[4][4], bh[4][4];
#pragma unroll
            for (int mt = 0; mt < 4; mt++) ldsm4(ah[mt], stg + aoffA[mt][ks]);
#pragma unroll
            for (int nt2 = 0; nt2 < 4; nt2++) ldsm4(bh[nt2], stg + aoffB[nt2][ks]);
#pragma unroll
            for (int mt = 0; mt < 4; mt++)
#pragma unroll
                for (int nt = 0; nt < 8; nt++)
                    mma16816h(acc[mt][nt], ah[mt], &bh[nt >> 1][(nt & 1) * 2]);
        }
        __syncthreads();
    }

    float* norm_sm = (float*)(smem + 2 * GSM_STAGE);
    if (t < 128) norm_sm[t] = 0.f;
    __syncthreads();

    float2 bias2[8];
#pragma unroll
    for (int nt = 0; nt < 8; nt++)
        bias2[nt] = *(const float2*)&bias[bn * 256 + wn * 64 + nt * 8 + (l & 3) * 2];

#pragma unroll
    for (int mt = 0; mt < 4; mt++)
#pragma unroll
        for (int half = 0; half < 2; half++) {
            int r = wm * 64 + mt * 16 + (l >> 2) + half * 8;
            float ss = 0.f;
#pragma unroll
            for (int nt = 0; nt < 8; nt++) {
                float2 v = __half22float2(*(__half2*)&acc[mt][nt][half]);
                float vx = v.x + bias2[nt].x;
                float vy = v.y + bias2[nt].y;
                ss += vx * vx + vy * vy;
            }
            ss += __shfl_xor_sync(0xffffffffu, ss, 1);
            ss += __shfl_xor_sync(0xffffffffu, ss, 2);
            if ((l & 3) == 0) atomicAdd(&norm_sm[r], ss);
        }
    __syncthreads();
    if (t < 128)
        g_norms[(size_t)bn * M_ROWS + (size_t)mtile * 128 + t] = norm_sm[t];
}

// ============================================================================
// pass0: iteration 0 uniform softmax. scales -> g_scale, y0 partials, Wp.
// ============================================================================
__global__ void __launch_bounds__(256) pass0_kernel() {
    const int c = blockIdx.y, chunk = blockIdx.x;
    const int t = threadIdx.x, wid = t >> 5, lane = t & 31;
    __shared__ float ssc[CHUNK_S];
    __shared__ float wred[4];

    const size_t rowbase = (size_t)c * S_DIM + (size_t)chunk * CHUNK_S;
    if (t < CHUNK_S) {
        size_t row = rowbase + t;
        float sq = g_norms[row] + g_norms[M_ROWS + row];
        float s = (sq / (1.f + sq)) * rsqrtf(sq + 1e-7f);
        ssc[t] = s;
        g_scale[row] = s;
    }
    __syncthreads();

    float ax = 0.f, ay = 0.f;
    const __half2* xp = (const __half2*)(g_xhf + rowbase * 512) + t;
#pragma unroll 8
    for (int s = 0; s < CHUNK_S; s++) {
        float2 v = __half22float2(xp[s * 256]);
        float w = ssc[s];
        ax += w * v.x;
        ay += w * v.y;
    }
    int pc = c * NCHUNK + chunk;
    *(float2*)&g_Vp[(size_t)pc * 512 + 2 * t] = make_float2(ax, ay);

    if (t < CHUNK_S) {
        float p = ssc[t];
#pragma unroll
        for (int off = 16; off > 0; off >>= 1)
            p += __shfl_xor_sync(0xffffffffu, p, off);
        if (lane == 0) wred[wid] = p;
    }
    __syncthreads();
    if (t == 0) {
        g_Mp[pc] = 0.f;
        g_Zp[pc] = (float)CHUNK_S;
        g_Wp[pc] = wred[0] + wred[1] + wred[2] + wred[3];
    }
}

// ============================================================================
// Sweep (iterations 1,2): fp16 x, 3-slot cp.async ring, 32-row stages.
// Applies capsule scale to u/bc on load (u,bc are stored UNSCALED).
// ============================================================================
#define SWEEP_SMEM (SLOTS * RSTG * 512 * 2)

__device__ __forceinline__ void sweep_issue(const __half* src, __half* slot, int t) {
    uint32_t dst = smem_u32(slot);
    const char* s = (const char*)src;
#pragma unroll
    for (int i = 0; i < 8; i++) {
        int idx = t + 256 * i;
        CP_ASYNC16(dst + idx * 16, s + idx * 16);
    }
    CP_COMMIT();
}

__global__ void __launch_bounds__(256, 2) sweep_pass(int first, int store_b) {
    extern __shared__ __align__(16) __half tiles[];
    __shared__ float usm[512];
    __shared__ float bst[RSTG], wst[RSTG];
    __shared__ float runMs, Zsh, Wsh, fsh, bcs;

    const int c = blockIdx.y, chunk = blockIdx.x;
    const int t = threadIdx.x, wid = t >> 5, lane = t & 31;

    // capsule squash scale (from sumsq partials) applied to unscaled u / bc
    float sqc = g_sqp[c * 8] + g_sqp[c * 8 + 1] + g_sqp[c * 8 + 2] + g_sqp[c * 8 + 3]
              + g_sqp[c * 8 + 4] + g_sqp[c * 8 + 5] + g_sqp[c * 8 + 6] + g_sqp[c * 8 + 7];
    float scc = (sqc / (1.f + sqc)) * rsqrtf(sqc + 1e-7f);

    usm[t]       = g_u[c * 512 + t] * scc;
    usm[t + 256] = g_u[c * 512 + t + 256] * scc;
    if (t == 0) { runMs = -1e30f; Zsh = 0.f; Wsh = 0.f; bcs = g_bc[c] * scc; }

    const size_t rowbase = (size_t)c * S_DIM + (size_t)chunk * CHUNK_S;
    const __half* xsrc = g_xhf + rowbase * 512;
    float ax = 0.f, ay = 0.f;

    sweep_issue(xsrc, tiles, t);
    sweep_issue(xsrc + (size_t)RSTG * 512, tiles + RSTG * 512, t);

    for (int st = 0; st < NSTG; st++) {
        if (st < NSTG - 1) { CP_WAIT(1); } else { CP_WAIT(0); }
        __syncthreads();
        __half* tile = tiles + (st % SLOTS) * (RSTG * 512);

        if (st + 2 < NSTG)
            sweep_issue(xsrc + (size_t)(st + 2) * RSTG * 512,
                        tiles + ((st + 2) % SLOTS) * (RSTG * 512), t);

#pragma unroll
        for (int rr = 0; rr < 4; rr++) {
            int rl = wid * 4 + rr;
            const __half2* tr = (const __half2*)(tile + rl * 512);
            float dot = 0.f;
#pragma unroll
            for (int j = 0; j < 8; j++) {
                float2 v = __half22float2(tr[lane + 32 * j]);
                float2 cv = *(const float2*)&usm[(lane + 32 * j) * 2];
                dot += v.x * cv.x + v.y * cv.y;
            }
#pragma unroll
            for (int off = 16; off > 0; off >>= 1)
                dot += __shfl_xor_sync(0xffffffffu, dot, off);
            if (lane == 0) {
                size_t row = rowbase + st * RSTG + rl;
                float scale = g_scale[row];
                float bv = scale * (dot + bcs);
                if (!first) bv += g_b[row];
                if (store_b) g_b[row] = bv;
                bst[rl] = bv;
                wst[rl] = scale;
            }
        }
        __syncthreads();

        if (t < 32) {
            float v = bst[lane];
            float sc = wst[lane];
            float m = v;
#pragma unroll
            for (int off = 16; off > 0; off >>= 1)
                m = fmaxf(m, __shfl_xor_sync(0xffffffffu, m, off));
            float rm = runMs;
            float nm = fmaxf(rm, m);
            float w = __expf(v - nm);
            float zst = w;
#pragma unroll
            for (int off = 16; off > 0; off >>= 1)
                zst += __shfl_xor_sync(0xffffffffu, zst, off);
            float wsv = w * sc;
            float wss = wsv;
#pragma unroll
            for (int off = 16; off > 0; off >>= 1)
                wss += __shfl_xor_sync(0xffffffffu, wss, off);
            wst[lane] = wsv;
            if (lane == 0) {
                float f = __expf(rm - nm);
                fsh = f;
                Zsh = Zsh * f + zst;
                Wsh = Wsh * f + wss;
                runMs = nm;
            }
        }
        __syncthreads();

        float f = fsh;
        ax *= f; ay *= f;
        const __half2* col = (const __half2*)(tile + 2 * t);
#pragma unroll
        for (int r = 0; r < RSTG; r++) {
            float w = wst[r];
            float2 v = __half22float2(col[r * 256]);
            ax += w * v.x;
            ay += w * v.y;
        }
    }

    int pc = c * NCHUNK + chunk;
    *(float2*)&g_Vp[(size_t)pc * 512 + 2 * t] = make_float2(ax, ay);
    if (t == 0) { g_Mp[pc] = runMs; g_Zp[pc] = Zsh; g_Wp[pc] = Wsh; }
}

// ============================================================================
// cmat (fused reduce + optional u step): y from chunk partials;
// craw = y.W_o + bias_o*wts; partial sumsq; if do_u: atomically accumulate
// UNSCALED u' = W^T craw and bc' = bias.craw (scale applied in next sweep).
// grid (8, 64).
// ============================================================================
__global__ void __launch_bounds__(256) cmat_kernel(
    const float* __restrict__ W, const float* __restrict__ bias, int do_u)
{
    const int ob = blockIdx.x, c = blockIdx.y;
    const int t = threadIdx.x, wid = t >> 5, lane = t & 31;
    __shared__ float ysm[512];
    __shared__ float sk[NCHUNK];
    __shared__ float ssp[8];
    __shared__ float bcp[8];
    __shared__ float u_w[8][512];   // per-warp unscaled u' slabs
    __shared__ float Zs, Wts;

    if (t == 0) {
        float M = g_Mp[c * NCHUNK];
#pragma unroll
        for (int k = 1; k < NCHUNK; k++) M = fmaxf(M, g_Mp[c * NCHUNK + k]);
        float Z = 0.f, Wt = 0.f;
#pragma unroll
        for (int k = 0; k < NCHUNK; k++) {
            float e = __expf(g_Mp[c * NCHUNK + k] - M);
            sk[k] = e;
            Z  += g_Zp[c * NCHUNK + k] * e;
            Wt += g_Wp[c * NCHUNK + k] * e;
        }
        Zs = Z;
        Wts = Wt / Z;
    }
    __syncthreads();

    {
        float w0 = 0.f, w1 = 0.f;
#pragma unroll
        for (int k = 0; k < NCHUNK; k++) {
            float e = sk[k];
            float2 v = *(const float2*)&g_Vp[((size_t)(c * NCHUNK + k)) * 512 + 2 * t];
            w0 += e * v.x;
            w1 += e * v.y;
        }
        float invZ = 1.f / Zs;
        ysm[2 * t] = w0 * invZ;
        ysm[2 * t + 1] = w1 * invZ;
    }
    __syncthreads();

    const float Wts_l = Wts;
    float ss = 0.f, bcl = 0.f;
    float4 ua0 = {0,0,0,0}, ua1 = {0,0,0,0}, ua2 = {0,0,0,0}, ua3 = {0,0,0,0};

#pragma unroll
    for (int i = 0; i < 8; i++) {
        int o = ob * 64 + wid * 8 + i;
        const float4* wr = (const float4*)(W + (size_t)o * 512);
        float4 a0 = wr[lane], a1 = wr[lane + 32], a2 = wr[lane + 64], a3 = wr[lane + 96];
        float4 b0 = *(const float4*)&ysm[lane * 4];
        float4 b1 = *(const float4*)&ysm[(lane + 32) * 4];
        float4 b2 = *(const float4*)&ysm[(lane + 64) * 4];
        float4 b3 = *(const float4*)&ysm[(lane + 96) * 4];
        float d = a0.x * b0.x + a0.y * b0.y + a0.z * b0.z + a0.w * b0.w
                + a1.x * b1.x + a1.y * b1.y + a1.z * b1.z + a1.w * b1.w
                + a2.x * b2.x + a2.y * b2.y + a2.z * b2.z + a2.w * b2.w
                + a3.x * b3.x + a3.y * b3.y + a3.z * b3.z + a3.w * b3.w;
#pragma unroll
        for (int off = 16; off > 0; off >>= 1)
            d += __shfl_xor_sync(0xffffffffu, d, off);
        float cr = d + bias[o] * Wts_l;     // full value in ALL lanes
        if (lane == 0) {
            g_craw[c * 512 + o] = cr;
            ss += cr * cr;
            bcl += bias[o] * cr;
        }
        if (do_u) {
            ua0.x += cr * a0.x; ua0.y += cr * a0.y; ua0.z += cr * a0.z; ua0.w += cr * a0.w;
            ua1.x += cr * a1.x; ua1.y += cr * a1.y; ua1.z += cr * a1.z; ua1.w += cr * a1.w;
            ua2.x += cr * a2.x; ua2.y += cr * a2.y; ua2.z += cr * a2.z; ua2.w += cr * a2.w;
            ua3.x += cr * a3.x; ua3.y += cr * a3.y; ua3.z += cr * a3.z; ua3.w += cr * a3.w;
        }
    }
    if (lane == 0) { ssp[wid] = ss; bcp[wid] = bcl; }

    if (do_u) {
        *(float4*)&u_w[wid][lane * 4]        = ua0;
        *(float4*)&u_w[wid][(lane + 32) * 4] = ua1;
        *(float4*)&u_w[wid][(lane + 64) * 4] = ua2;
        *(float4*)&u_w[wid][(lane + 96) * 4] = ua3;
    }
    __syncthreads();

    if (do_u) {
#pragma unroll
        for (int half = 0; half < 2; half++) {
            int k = t + half * 256;
            float s = 0.f;
#pragma unroll
            for (int w = 0; w < 8; w++) s += u_w[w][k];
            atomicAdd(&g_u[c * 512 + k], s);
        }
    }
    if (t == 0) {
        float s = 0.f, bb = 0.f;
#pragma unroll
        for (int k = 0; k < 8; k++) { s += ssp[k]; bb += bcp[k]; }
        g_sqp[c * 8 + ob] = s;
        if (do_u) atomicAdd(&g_bc[c], bb);
    }
}

// ============================================================================
__global__ void __launch_bounds__(256) out_kernel(float* __restrict__ out) {
    const int c = blockIdx.x, t = threadIdx.x;
    __shared__ float scsh;
    if (t == 0) {
        float sq = 0.f;
#pragma unroll
        for (int k = 0; k < 8; k++) sq += g_sqp[c * 8 + k];
        scsh = (sq / (1.f + sq)) * rsqrtf(sq + 1e-7f);
    }
    __syncthreads();
    out[c * 512 + t]       = scsh * g_craw[c * 512 + t];
    out[c * 512 + t + 256] = scsh * g_craw[c * 512 + t + 256];
}

// ============================================================================
extern "C" void kernel_launch(void* const* d_in, const int* in_sizes, int n_in,
                              void* d_out, int out_size) {
    const float* x    = (const float*)d_in[0];
    const float* W    = (const float*)d_in[1];
    const float* bias = (const float*)d_in[2];
    float* out = (float*)d_out;

    void* pu = nullptr; cudaGetSymbolAddress(&pu, g_u);
    void* pbc = nullptr; cudaGetSymbolAddress(&pbc, g_bc);

    convw_kernel<<<256, 256>>>(W);

    static bool attr_done = false;
    if (!attr_done) {
        cudaFuncSetAttribute(gemm_norms, cudaFuncAttributeMaxDynamicSharedMemorySize, GSM_TOTAL);
        cudaFuncSetAttribute(sweep_pass, cudaFuncAttributeMaxDynamicSharedMemorySize, SWEEP_SMEM);
        attr_done = true;
    }
    gemm_norms<<<dim3(2, 1024), 256, GSM_TOTAL>>>(x, bias);

    // iteration 0 (uniform softmax)
    pass0_kernel<<<dim3(NCHUNK, C_CAPS), 256>>>();
    cudaMemsetAsync(pu, 0, C_CAPS * H_DIM * sizeof(float));
    cudaMemsetAsync(pbc, 0, C_CAPS * sizeof(float));
    cmat_kernel<<<dim3(8, C_CAPS), 256>>>(W, bias, 1);

    // iteration 1
    sweep_pass<<<dim3(NCHUNK, C_CAPS), 256, SWEEP_SMEM>>>(1, 1);
    cudaMemsetAsync(pu, 0, C_CAPS * H_DIM * sizeof(float));
    cudaMemsetAsync(pbc, 0, C_CAPS * sizeof(float));
    cmat_kernel<<<dim3(8, C_CAPS), 256>>>(W, bias, 1);

    // iteration 2
    sweep_pass<<<dim3(NCHUNK, C_CAPS), 256, SWEEP_SMEM>>>(0, 0);
    cmat_kernel<<<dim3(8, C_CAPS), 256>>>(W, bias, 0);
    out_kernel<<<C_CAPS, 256>>>(out);
}

// round 17
// speedup vs baseline: 1.3068x; 1.0114x over previous
#include <cuda_runtime.h>
#include <cuda_fp16.h>
#include <cstdint>

#define C_CAPS 64
#define S_DIM 2048
#define H_DIM 512
#define M_ROWS (C_CAPS * S_DIM)   // 131072
#define NCHUNK 16
#define CHUNK_S (S_DIM / NCHUNK)  // 128
#define RSTG 32
#define NSTG (CHUNK_S / RSTG)     // 4
#define SLOTS 3

// ---------------- device scratch ----------------
__device__ __align__(128) __half g_whf[(size_t)H_DIM * H_DIM];   // pre-swizzled fp16 W
__device__ __align__(128) __half g_xhf[(size_t)M_ROWS * H_DIM];  // linear fp16 x
__device__ float g_norms[2 * M_ROWS];
__device__ float g_scale[M_ROWS];
__device__ float g_b[M_ROWS];
__device__ float g_u[C_CAPS * H_DIM];      // UNSCALED W^T craw (atomic-accumulated)
__device__ float g_bc[C_CAPS];             // UNSCALED bias.craw
__device__ float g_Mp[C_CAPS * NCHUNK];
__device__ float g_Zp[C_CAPS * NCHUNK];
__device__ float g_Wp[C_CAPS * NCHUNK];
__device__ float g_Vp[(size_t)C_CAPS * NCHUNK * H_DIM];
__device__ float g_craw[C_CAPS * H_DIM];
__device__ float g_sqp[C_CAPS * 8];

// ---------------- helpers ----------------
__device__ __forceinline__ uint32_t smem_u32(const void* p) {
    uint32_t a;
    asm("{ .reg .u64 t; cvta.to.shared.u64 t, %1; cvt.u32.u64 %0, t; }" : "=r"(a) : "l"(p));
    return a;
}
__device__ __forceinline__ void ldsm4(uint32_t* r, uint32_t addr) {
    asm volatile("ldmatrix.sync.aligned.m8n8.x4.shared.b16 {%0,%1,%2,%3}, [%4];"
        : "=r"(r[0]), "=r"(r[1]), "=r"(r[2]), "=r"(r[3]) : "r"(addr));
}
__device__ __forceinline__ void mma16816h(uint32_t* d, const uint32_t* a, const uint32_t* b) {
    asm volatile("mma.sync.aligned.m16n8k16.row.col.f16.f16.f16.f16 "
        "{%0,%1}, {%2,%3,%4,%5}, {%6,%7}, {%0,%1};"
        : "+r"(d[0]), "+r"(d[1])
        : "r"(a[0]), "r"(a[1]), "r"(a[2]), "r"(a[3]), "r"(b[0]), "r"(b[1]));
}
__device__ __forceinline__ void sts128(uint32_t addr, uint4 v) {
    asm volatile("st.shared.v4.b32 [%0], {%1,%2,%3,%4};"
        :: "r"(addr), "r"(v.x), "r"(v.y), "r"(v.z), "r"(v.w) : "memory");
}
#define CP_ASYNC16(dst, src) \
    asm volatile("cp.async.cg.shared.global [%0], [%1], 16;" :: "r"(dst), "l"(src) : "memory")
#define CP_COMMIT() asm volatile("cp.async.commit_group;" ::: "memory")
#define CP_WAIT(n)  asm volatile("cp.async.wait_group %0;" :: "n"(n) : "memory")

__device__ __forceinline__ uint32_t packh2(float x, float y) {
    __half2 h = __floats2half2_rn(x, y);
    return *(uint32_t*)&h;
}
__device__ __forceinline__ uint32_t tswz(uint32_t row, uint32_t kc) {
    return row * 64u + ((kc ^ ((row >> 1) & 3u)) << 4);
}

// ============================================================================
// convw: W fp32 -> pre-swizzled fp16 tiles (8KB blocks [128 rows x 32 k]).
// ============================================================================
__global__ void convw_kernel(const float* __restrict__ W) {
    int g = blockIdx.x * 256 + threadIdx.x;
    int n = g >> 7, ch = g & 127;
    int kt = ch >> 3, kc = (ch >> 1) & 3, half = ch & 1;
    int bn = n >> 7, nrow = n & 127;
    float4 v = *(const float4*)&W[(size_t)n * 512 + ch * 4];
    uint2 hi;
    hi.x = packh2(v.x, v.y);
    hi.y = packh2(v.z, v.w);
    size_t dst = ((size_t)(bn * 16 + kt) << 13) + tswz(nrow, kc) + half * 8;
    *(uint2*)((char*)g_whf + dst) = hi;
}

// ============================================================================
// GEMM (norms only): CTA 128x256, warp tile 64x64, BK=32, f16-acc HMMA.
// bn==0 blocks export fp16 x to g_xhf.
// ============================================================================
#define GSM_STAGE 24576
#define GSM_TOTAL (2 * GSM_STAGE + 512)

__device__ __forceinline__ void issueB(uint32_t stg, int bn, int kt, int t) {
    size_t t0 = (size_t)((bn * 2) * 16 + kt) << 13;
    size_t t1 = (size_t)((bn * 2 + 1) * 16 + kt) << 13;
    const char* s0 = (const char*)g_whf + t0 + t * 32;
    const char* s1 = (const char*)g_whf + t1 + t * 32;
    CP_ASYNC16(stg + 8192 + t * 32, s0);
    CP_ASYNC16(stg + 8192 + t * 32 + 16, s0 + 16);
    CP_ASYNC16(stg + 16384 + t * 32, s1);
    CP_ASYNC16(stg + 16384 + t * 32 + 16, s1 + 16);
}

__global__ void __launch_bounds__(256, 2) gemm_norms(
    const float* __restrict__ x, const float* __restrict__ bias)
{
    extern __shared__ __align__(1024) char smem[];
    const uint32_t sb = smem_u32(smem);

    const int t = threadIdx.x, l = t & 31, wid = t >> 5;
    const int wm = wid & 1, wn = wid >> 1;
    const int bn = blockIdx.x, mtile = blockIdx.y;

    const int c0row = t >> 2, ckc = t & 3;
    const float* ag0 = x + ((size_t)mtile * 128 + c0row) * 512 + ckc * 8;
    const float* ag1 = x + ((size_t)mtile * 128 + c0row + 64) * 512 + ckc * 8;
    const uint32_t so0 = tswz(c0row, ckc);
    const uint32_t so1 = tswz(c0row + 64, ckc);

    __half* xo0 = g_xhf + ((size_t)mtile * 128 + c0row) * 512 + ckc * 8;
    __half* xo1 = g_xhf + ((size_t)mtile * 128 + c0row + 64) * 512 + ckc * 8;

    uint32_t aoffA[4][2], aoffB[4][2];
#pragma unroll
    for (int mt = 0; mt < 4; mt++)
#pragma unroll
        for (int ks = 0; ks < 2; ks++) {
            uint32_t m = wm * 64 + mt * 16 + ((l >> 3) & 1) * 8 + (l & 7);
            aoffA[mt][ks] = tswz(m, ks * 2 + (l >> 4));
        }
#pragma unroll
    for (int nt2 = 0; nt2 < 4; nt2++)
#pragma unroll
        for (int ks = 0; ks < 2; ks++) {
            uint32_t n = wn * 64 + nt2 * 16 + ((l >> 4) & 1) * 8 + (l & 7);
            uint32_t blk = n >> 7;
            aoffB[nt2][ks] = 8192 + blk * 8192 + tswz(n & 127, ks * 2 + ((l >> 3) & 1));
        }

    uint32_t acc[4][8][2];
#pragma unroll
    for (int mt = 0; mt < 4; mt++)
#pragma unroll
        for (int nt = 0; nt < 8; nt++) { acc[mt][nt][0] = 0u; acc[mt][nt][1] = 0u; }

    issueB(sb, bn, 0, t);
    CP_COMMIT();
    uint4 ha0, ha1;
    {
        float4 p0 = *(const float4*)(ag0), p1 = *(const float4*)(ag0 + 4);
        float4 p2 = *(const float4*)(ag1), p3 = *(const float4*)(ag1 + 4);
        ha0.x = packh2(p0.x, p0.y); ha0.y = packh2(p0.z, p0.w);
        ha0.z = packh2(p1.x, p1.y); ha0.w = packh2(p1.z, p1.w);
        ha1.x = packh2(p2.x, p2.y); ha1.y = packh2(p2.z, p2.w);
        ha1.z = packh2(p3.x, p3.y); ha1.w = packh2(p3.z, p3.w);
    }

    for (int kt = 0; kt < 16; kt++) {
        const uint32_t stg = sb + (kt & 1) * GSM_STAGE;
        sts128(stg + so0, ha0);
        sts128(stg + so1, ha1);
        if (bn == 0) {
            *(uint4*)(xo0 + kt * 32) = ha0;
            *(uint4*)(xo1 + kt * 32) = ha1;
        }
        if (kt < 15) {
            issueB(sb + ((kt + 1) & 1) * GSM_STAGE, bn, kt + 1, t);
            CP_COMMIT();
            CP_WAIT(1);
        } else {
            CP_WAIT(0);
        }
        __syncthreads();

        if (kt < 15) {
            int ko = (kt + 1) * 32;
            float4 p0 = *(const float4*)(ag0 + ko), p1 = *(const float4*)(ag0 + ko + 4);
            float4 p2 = *(const float4*)(ag1 + ko), p3 = *(const float4*)(ag1 + ko + 4);
            ha0.x = packh2(p0.x, p0.y); ha0.y = packh2(p0.z, p0.w);
            ha0.z = packh2(p1.x, p1.y); ha0.w = packh2(p1.z, p1.w);
            ha1.x = packh2(p2.x, p2.y); ha1.y = packh2(p2.z, p2.w);
            ha1.z = packh2(p3.x, p3.y); ha1.w = packh2(p3.z, p3.w);
        }

#pragma unroll
        for (int ks = 0; ks < 2; ks++) {
            uint32_t ah[4][4], bh[4][4];
#pragma unroll
            for (int mt = 0; mt < 4; mt++) ldsm4(ah[mt], stg + aoffA[mt][ks]);
#pragma unroll
            for (int nt2 = 0; nt2 < 4; nt2++) ldsm4(bh[nt2], stg + aoffB[nt2][ks]);
#pragma unroll
            for (int mt = 0; mt < 4; mt++)
#pragma unroll
                for (int nt = 0; nt < 8; nt++)
                    mma16816h(acc[mt][nt], ah[mt], &bh[nt >> 1][(nt & 1) * 2]);
        }
        __syncthreads();
    }

    float* norm_sm = (float*)(smem + 2 * GSM_STAGE);
    if (t < 128) norm_sm[t] = 0.f;
    __syncthreads();

    float2 bias2[8];
#pragma unroll
    for (int nt = 0; nt < 8; nt++)
        bias2[nt] = *(const float2*)&bias[bn * 256 + wn * 64 + nt * 8 + (l & 3) * 2];

#pragma unroll
    for (int mt = 0; mt < 4; mt++)
#pragma unroll
        for (int half = 0; half < 2; half++) {
            int r = wm * 64 + mt * 16 + (l >> 2) + half * 8;
            float ss = 0.f;
#pragma unroll
            for (int nt = 0; nt < 8; nt++) {
                float2 v = __half22float2(*(__half2*)&acc[mt][nt][half]);
                float vx = v.x + bias2[nt].x;
                float vy = v.y + bias2[nt].y;
                ss += vx * vx + vy * vy;
            }
            ss += __shfl_xor_sync(0xffffffffu, ss, 1);
            ss += __shfl_xor_sync(0xffffffffu, ss, 2);
            if ((l & 3) == 0) atomicAdd(&norm_sm[r], ss);
        }
    __syncthreads();
    if (t < 128)
        g_norms[(size_t)bn * M_ROWS + (size_t)mtile * 128 + t] = norm_sm[t];
}

// ============================================================================
// pass0: iteration 0 uniform softmax. scales -> g_scale, y0 partials, Wp.
// ============================================================================
__global__ void __launch_bounds__(256) pass0_kernel() {
    const int c = blockIdx.y, chunk = blockIdx.x;
    const int t = threadIdx.x, wid = t >> 5, lane = t & 31;
    __shared__ float ssc[CHUNK_S];
    __shared__ float wred[4];

    const size_t rowbase = (size_t)c * S_DIM + (size_t)chunk * CHUNK_S;
    if (t < CHUNK_S) {
        size_t row = rowbase + t;
        float sq = g_norms[row] + g_norms[M_ROWS + row];
        float s = (sq / (1.f + sq)) * rsqrtf(sq + 1e-7f);
        ssc[t] = s;
        g_scale[row] = s;
    }
    __syncthreads();

    float ax = 0.f, ay = 0.f;
    const __half2* xp = (const __half2*)(g_xhf + rowbase * 512) + t;
#pragma unroll 8
    for (int s = 0; s < CHUNK_S; s++) {
        float2 v = __half22float2(xp[s * 256]);
        float w = ssc[s];
        ax += w * v.x;
        ay += w * v.y;
    }
    int pc = c * NCHUNK + chunk;
    *(float2*)&g_Vp[(size_t)pc * 512 + 2 * t] = make_float2(ax, ay);

    if (t < CHUNK_S) {
        float p = ssc[t];
#pragma unroll
        for (int off = 16; off > 0; off >>= 1)
            p += __shfl_xor_sync(0xffffffffu, p, off);
        if (lane == 0) wred[wid] = p;
    }
    __syncthreads();
    if (t == 0) {
        g_Mp[pc] = 0.f;
        g_Zp[pc] = (float)CHUNK_S;
        g_Wp[pc] = wred[0] + wred[1] + wred[2] + wred[3];
    }
}

// ============================================================================
// Sweep (iterations 1,2): fp16 x, 3-slot cp.async ring, 32-row stages,
// 2 barriers/stage (warp-redundant softmax bookkeeping + shfl weight bcast).
// Applies capsule scale to u/bc on load (stored UNSCALED).
// ============================================================================
#define SWEEP_SMEM (SLOTS * RSTG * 512 * 2)

__device__ __forceinline__ void sweep_issue(const __half* src, __half* slot, int t) {
    uint32_t dst = smem_u32(slot);
    const char* s = (const char*)src;
#pragma unroll
    for (int i = 0; i < 8; i++) {
        int idx = t + 256 * i;
        CP_ASYNC16(dst + idx * 16, s + idx * 16);
    }
    CP_COMMIT();
}

__global__ void __launch_bounds__(256, 2) sweep_pass(int first, int store_b) {
    extern __shared__ __align__(16) __half tiles[];
    __shared__ float usm[512];
    __shared__ float bst[RSTG], sst[RSTG];

    const int c = blockIdx.y, chunk = blockIdx.x;
    const int t = threadIdx.x, wid = t >> 5, lane = t & 31;

    float sqc = g_sqp[c * 8] + g_sqp[c * 8 + 1] + g_sqp[c * 8 + 2] + g_sqp[c * 8 + 3]
              + g_sqp[c * 8 + 4] + g_sqp[c * 8 + 5] + g_sqp[c * 8 + 6] + g_sqp[c * 8 + 7];
    float scc = (sqc / (1.f + sqc)) * rsqrtf(sqc + 1e-7f);

    usm[t]       = g_u[c * 512 + t] * scc;
    usm[t + 256] = g_u[c * 512 + t + 256] * scc;
    const float bcs = g_bc[c] * scc;

    // warp-private online softmax state (identical across warps)
    float runM = -1e30f, Zpr = 0.f, Wpr = 0.f;

    const size_t rowbase = (size_t)c * S_DIM + (size_t)chunk * CHUNK_S;
    const __half* xsrc = g_xhf + rowbase * 512;
    float ax = 0.f, ay = 0.f;

    sweep_issue(xsrc, tiles, t);
    sweep_issue(xsrc + (size_t)RSTG * 512, tiles + RSTG * 512, t);

    for (int st = 0; st < NSTG; st++) {
        if (st < NSTG - 1) { CP_WAIT(1); } else { CP_WAIT(0); }
        __syncthreads();
        __half* tile = tiles + (st % SLOTS) * (RSTG * 512);

        if (st + 2 < NSTG)
            sweep_issue(xsrc + (size_t)(st + 2) * RSTG * 512,
                        tiles + ((st + 2) % SLOTS) * (RSTG * 512), t);

        // dots: each warp handles 4 rows
#pragma unroll
        for (int rr = 0; rr < 4; rr++) {
            int rl = wid * 4 + rr;
            const __half2* tr = (const __half2*)(tile + rl * 512);
            float dot = 0.f;
#pragma unroll
            for (int j = 0; j < 8; j++) {
                float2 v = __half22float2(tr[lane + 32 * j]);
                float2 cv = *(const float2*)&usm[(lane + 32 * j) * 2];
                dot += v.x * cv.x + v.y * cv.y;
            }
#pragma unroll
            for (int off = 16; off > 0; off >>= 1)
                dot += __shfl_xor_sync(0xffffffffu, dot, off);
            if (lane == 0) {
                size_t row = rowbase + st * RSTG + rl;
                float scale = g_scale[row];
                float bv = scale * (dot + bcs);
                if (!first) bv += g_b[row];
                if (store_b) g_b[row] = bv;
                bst[rl] = bv;
                sst[rl] = scale;
            }
        }
        __syncthreads();

        // every warp redundantly computes the identical softmax update
        float v = bst[lane];
        float sc = sst[lane];
        float m = v;
#pragma unroll
        for (int off = 16; off > 0; off >>= 1)
            m = fmaxf(m, __shfl_xor_sync(0xffffffffu, m, off));
        float nm = fmaxf(runM, m);
        float w = __expf(v - nm);
        float zst = w;
#pragma unroll
        for (int off = 16; off > 0; off >>= 1)
            zst += __shfl_xor_sync(0xffffffffu, zst, off);
        float wsv = w * sc;
        float wss = wsv;
#pragma unroll
        for (int off = 16; off > 0; off >>= 1)
            wss += __shfl_xor_sync(0xffffffffu, wss, off);
        float f = __expf(runM - nm);
        Zpr = Zpr * f + zst;
        Wpr = Wpr * f + wss;
        runM = nm;

        ax *= f; ay *= f;
        const __half2* col = (const __half2*)(tile + 2 * t);
#pragma unroll
        for (int r = 0; r < RSTG; r++) {
            float wr = __shfl_sync(0xffffffffu, wsv, r);
            float2 vv = __half22float2(col[r * 256]);
            ax += wr * vv.x;
            ay += wr * vv.y;
        }
    }

    int pc = c * NCHUNK + chunk;
    *(float2*)&g_Vp[(size_t)pc * 512 + 2 * t] = make_float2(ax, ay);
    if (t == 0) { g_Mp[pc] = runM; g_Zp[pc] = Zpr; g_Wp[pc] = Wpr; }
}

// ============================================================================
// cmat (fused reduce + optional u step): y from chunk partials;
// craw = y.W_o + bias_o*wts; partial sumsq; if do_u: accumulate UNSCALED
// u' = W^T craw and bc' = bias.craw (scale applied in next sweep).
// ============================================================================
__global__ void __launch_bounds__(256) cmat_kernel(
    const float* __restrict__ W, const float* __restrict__ bias, int do_u)
{
    const int ob = blockIdx.x, c = blockIdx.y;
    const int t = threadIdx.x, wid = t >> 5, lane = t & 31;
    __shared__ float ysm[512];
    __shared__ float sk[NCHUNK];
    __shared__ float ssp[8];
    __shared__ float bcp[8];
    __shared__ float u_w[8][512];
    __shared__ float Zs, Wts;

    if (t == 0) {
        float M = g_Mp[c * NCHUNK];
#pragma unroll
        for (int k = 1; k < NCHUNK; k++) M = fmaxf(M, g_Mp[c * NCHUNK + k]);
        float Z = 0.f, Wt = 0.f;
#pragma unroll
        for (int k = 0; k < NCHUNK; k++) {
            float e = __expf(g_Mp[c * NCHUNK + k] - M);
            sk[k] = e;
            Z  += g_Zp[c * NCHUNK + k] * e;
            Wt += g_Wp[c * NCHUNK + k] * e;
        }
        Zs = Z;
        Wts = Wt / Z;
    }
    __syncthreads();

    {
        float w0 = 0.f, w1 = 0.f;
#pragma unroll
        for (int k = 0; k < NCHUNK; k++) {
            float e = sk[k];
            float2 v = *(const float2*)&g_Vp[((size_t)(c * NCHUNK + k)) * 512 + 2 * t];
            w0 += e * v.x;
            w1 += e * v.y;
        }
        float invZ = 1.f / Zs;
        ysm[2 * t] = w0 * invZ;
        ysm[2 * t + 1] = w1 * invZ;
    }
    __syncthreads();

    const float Wts_l = Wts;
    float ss = 0.f, bcl = 0.f;
    float4 ua0 = {0,0,0,0}, ua1 = {0,0,0,0}, ua2 = {0,0,0,0}, ua3 = {0,0,0,0};

#pragma unroll
    for (int i = 0; i < 8; i++) {
        int o = ob * 64 + wid * 8 + i;
        const float4* wr = (const float4*)(W + (size_t)o * 512);
        float4 a0 = wr[lane], a1 = wr[lane + 32], a2 = wr[lane + 64], a3 = wr[lane + 96];
        float4 b0 = *(const float4*)&ysm[lane * 4];
        float4 b1 = *(const float4*)&ysm[(lane + 32) * 4];
        float4 b2 = *(const float4*)&ysm[(lane + 64) * 4];
        float4 b3 = *(const float4*)&ysm[(lane + 96) * 4];
        float d = a0.x * b0.x + a0.y * b0.y + a0.z * b0.z + a0.w * b0.w
                + a1.x * b1.x + a1.y * b1.y + a1.z * b1.z + a1.w * b1.w
                + a2.x * b2.x + a2.y * b2.y + a2.z * b2.z + a2.w * b2.w
                + a3.x * b3.x + a3.y * b3.y + a3.z * b3.z + a3.w * b3.w;
#pragma unroll
        for (int off = 16; off > 0; off >>= 1)
            d += __shfl_xor_sync(0xffffffffu, d, off);
        float cr = d + bias[o] * Wts_l;
        if (lane == 0) {
            g_craw[c * 512 + o] = cr;
            ss += cr * cr;
            bcl += bias[o] * cr;
        }
        if (do_u) {
            ua0.x += cr * a0.x; ua0.y += cr * a0.y; ua0.z += cr * a0.z; ua0.w += cr * a0.w;
            ua1.x += cr * a1.x; ua1.y += cr * a1.y; ua1.z += cr * a1.z; ua1.w += cr * a1.w;
            ua2.x += cr * a2.x; ua2.y += cr * a2.y; ua2.z += cr * a2.z; ua2.w += cr * a2.w;
            ua3.x += cr * a3.x; ua3.y += cr * a3.y; ua3.z += cr * a3.z; ua3.w += cr * a3.w;
        }
    }
    if (lane == 0) { ssp[wid] = ss; bcp[wid] = bcl; }

    if (do_u) {
        *(float4*)&u_w[wid][lane * 4]        = ua0;
        *(float4*)&u_w[wid][(lane + 32) * 4] = ua1;
        *(float4*)&u_w[wid][(lane + 64) * 4] = ua2;
        *(float4*)&u_w[wid][(lane + 96) * 4] = ua3;
    }
    __syncthreads();

    if (do_u) {
#pragma unroll
        for (int half = 0; half < 2; half++) {
            int k = t + half * 256;
            float s = 0.f;
#pragma unroll
            for (int w = 0; w < 8; w++) s += u_w[w][k];
            atomicAdd(&g_u[c * 512 + k], s);
        }
    }
    if (t == 0) {
        float s = 0.f, bb = 0.f;
#pragma unroll
        for (int k = 0; k < 8; k++) { s += ssp[k]; bb += bcp[k]; }
        g_sqp[c * 8 + ob] = s;
        if (do_u) atomicAdd(&g_bc[c], bb);
    }
}

// ============================================================================
__global__ void __launch_bounds__(256) out_kernel(float* __restrict__ out) {
    const int c = blockIdx.x, t = threadIdx.x;
    __shared__ float scsh;
    if (t == 0) {
        float sq = 0.f;
#pragma unroll
        for (int k = 0; k < 8; k++) sq += g_sqp[c * 8 + k];
        scsh = (sq / (1.f + sq)) * rsqrtf(sq + 1e-7f);
    }
    __syncthreads();
    out[c * 512 + t]       = scsh * g_craw[c * 512 + t];
    out[c * 512 + t + 256] = scsh * g_craw[c * 512 + t + 256];
}

// ============================================================================
extern "C" void kernel_launch(void* const* d_in, const int* in_sizes, int n_in,
                              void* d_out, int out_size) {
    const float* x    = (const float*)d_in[0];
    const float* W    = (const float*)d_in[1];
    const float* bias = (const float*)d_in[2];
    float* out = (float*)d_out;

    void* pu = nullptr; cudaGetSymbolAddress(&pu, g_u);
    void* pbc = nullptr; cudaGetSymbolAddress(&pbc, g_bc);

    convw_kernel<<<256, 256>>>(W);

    static bool attr_done = false;
    if (!attr_done) {
        cudaFuncSetAttribute(gemm_norms, cudaFuncAttributeMaxDynamicSharedMemorySize, GSM_TOTAL);
        cudaFuncSetAttribute(sweep_pass, cudaFuncAttributeMaxDynamicSharedMemorySize, SWEEP_SMEM);
        attr_done = true;
    }
    gemm_norms<<<dim3(2, 1024), 256, GSM_TOTAL>>>(x, bias);

    // iteration 0 (uniform softmax)
    pass0_kernel<<<dim3(NCHUNK, C_CAPS), 256>>>();
    cudaMemsetAsync(pu, 0, C_CAPS * H_DIM * sizeof(float));
    cudaMemsetAsync(pbc, 0, C_CAPS * sizeof(float));
    cmat_kernel<<<dim3(8, C_CAPS), 256>>>(W, bias, 1);

    // iteration 1
    sweep_pass<<<dim3(NCHUNK, C_CAPS), 256, SWEEP_SMEM>>>(1, 1);
    cudaMemsetAsync(pu, 0, C_CAPS * H_DIM * sizeof(float));
    cudaMemsetAsync(pbc, 0, C_CAPS * sizeof(float));
    cmat_kernel<<<dim3(8, C_CAPS), 256>>>(W, bias, 1);

    // iteration 2
    sweep_pass<<<dim3(NCHUNK, C_CAPS), 256, SWEEP_SMEM>>>(0, 0);
    cmat_kernel<<<dim3(8, C_CAPS), 256>>>(W, bias, 0);
    out_kernel<<<C_CAPS, 256>>>(out);
}